// round 5
// baseline (speedup 1.0000x reference)
#include <cuda_runtime.h>
#include <cuda_fp16.h>
#include <cstdint>

// ---------------------------------------------------------------------------
// LSTM Seq2Seq on GB300 — single persistent kernel (128 CTAs, grid barriers).
// Encoder: wave w computes layer0(t=w) and layer1(t=w-1) (independent).
// Decoder: 2 waves/step; fc heads via deterministic per-CTA partial sums.
// GEMM: fp16 mma.sync m16n8k16, 64x128 CTA tile, BK=32, 4-stage cp.async.
// ---------------------------------------------------------------------------

#define HIDDEN   512
#define BATCH    512
#define NFEAT    32
#define LAGS     96
#define HORIZONS 24
#define NGATE    2048
#define GRID_CTAS 128

// ---- byte-based scratch layout ----
#define OFF_WP0   0u
#define SZ_WP0B   (544u * 2048u * 2u)
#define OFF_WP1   (OFF_WP0 + SZ_WP0B)
#define SZ_WP1B   (1024u * 2048u * 2u)
#define OFF_WP2   (OFF_WP1 + SZ_WP1B)
#define OFF_WP3   (OFF_WP2 + SZ_WP0B)
#define OFF_BS    (OFF_WP3 + SZ_WP1B)                  // float[4*2048]
#define OFF_H     (OFF_BS + 4u * 2048u * 4u)           // half[2*2*512*512]
#define OFF_C     (OFF_H + 2u * 2u * 512u * 512u * 2u) // float[2*512*512]
#define OFF_XH    (OFF_C + 2u * 512u * 512u * 4u)      // half[96*512*32]
#define OFF_DECP  (OFF_XH + 96u * 512u * 32u * 2u)     // float[16*512*32]
#define OFF_FC1P  (OFF_DECP + 16u * 512u * 32u * 4u)   // float[16*512]
#define SCRATCH_BYTES (OFF_FC1P + 16u * 512u * 4u)

__device__ __align__(1024) unsigned char g_scratch[SCRATCH_BYTES];
__device__ unsigned int g_bar;

// ---------------------------------------------------------------------------
__device__ __forceinline__ uint32_t smem_u32(const void* p) {
    return (uint32_t)__cvta_generic_to_shared(p);
}
__device__ __forceinline__ void cpa16(uint32_t dst, const void* src) {
    asm volatile("cp.async.cg.shared.global [%0], [%1], 16;" :: "r"(dst), "l"(src));
}
__device__ __forceinline__ void cpa_commit() {
    asm volatile("cp.async.commit_group;" ::: "memory");
}
__device__ __forceinline__ void mma_f16(float* d, const uint32_t* a,
                                        uint32_t b0, uint32_t b1) {
    asm volatile(
        "mma.sync.aligned.m16n8k16.row.col.f32.f16.f16.f32 "
        "{%0,%1,%2,%3},{%4,%5,%6,%7},{%8,%9},{%0,%1,%2,%3};"
        : "+f"(d[0]), "+f"(d[1]), "+f"(d[2]), "+f"(d[3])
        : "r"(a[0]), "r"(a[1]), "r"(a[2]), "r"(a[3]), "r"(b0), "r"(b1));
}
__device__ __forceinline__ float fsigmoid(float x) { return 1.f / (1.f + __expf(-x)); }
__device__ __forceinline__ float ftanh(float x)    { return 2.f / (1.f + __expf(-2.f * x)) - 1.f; }

// grid-wide barrier: monotone counter, release/acquire
__device__ __forceinline__ void grid_sync(unsigned int target) {
    __syncthreads();
    if (threadIdx.x == 0) {
        __threadfence();
        asm volatile("red.add.release.gpu.global.u32 [%0], %1;"
                     :: "l"(&g_bar), "r"(1u) : "memory");
        unsigned int cur;
        do {
            asm volatile("ld.acquire.gpu.global.u32 %0, [%1];"
                         : "=r"(cur) : "l"(&g_bar) : "memory");
            if (cur >= target) break;
            __nanosleep(64);
        } while (true);
    }
    __syncthreads();
}

// ---------------------------------------------------------------------------
// Setup kernels
// ---------------------------------------------------------------------------
__global__ void pack_weights(const float* __restrict__ Wih,
                             const float* __restrict__ Whh,
                             int in_dim, int Ktot, __half* __restrict__ Wp, int total)
{
    int idx = blockIdx.x * blockDim.x + threadIdx.x;
    if (idx >= total) return;
    int n = idx / Ktot;
    int k = idx - n * Ktot;
    int j = n >> 2, g = n & 3;
    float v;
    if (k < in_dim) v = Wih[(g * HIDDEN + j) * in_dim + k];
    else            v = Whh[(g * HIDDEN + j) * HIDDEN + (k - in_dim)];
    Wp[idx] = __float2half_rn(v);
}

__global__ void pack_bias(const float* __restrict__ bih,
                          const float* __restrict__ bhh,
                          float* __restrict__ bs)
{
    int n = blockIdx.x * blockDim.x + threadIdx.x;
    if (n >= NGATE) return;
    int j = n >> 2, g = n & 3;
    bs[n] = bih[g * HIDDEN + j] + bhh[g * HIDDEN + j];
}

// src [B][96][32] fp32 -> xh [96][B][32] half
__global__ void convert_src(const float* __restrict__ src, __half* __restrict__ xh)
{
    int i = blockIdx.x * blockDim.x + threadIdx.x;
    if (i >= LAGS * BATCH * NFEAT) return;
    int t = i / (BATCH * NFEAT);
    int r = i - t * (BATCH * NFEAT);
    int b = r / NFEAT, f = r - b * NFEAT;
    xh[i] = __float2half_rn(src[b * (LAGS * NFEAT) + t * NFEAT + f]);
}

__global__ void zero_h(__half* __restrict__ p, int n)
{
    int i = blockIdx.x * blockDim.x + threadIdx.x;
    if (i < n) p[i] = __half(0.f);
}
__global__ void zero_f(float* __restrict__ p, int n)
{
    int i = blockIdx.x * blockDim.x + threadIdx.x;
    if (i < n) p[i] = 0.f;
}

// decx_part init: part0[b][f] = src[b][95][f] - fc4_b[f]; parts 1..15 = 0
__global__ void init_decp(const float* __restrict__ src,
                          const float* __restrict__ fc4_b,
                          float* __restrict__ decp)
{
    int i = blockIdx.x * blockDim.x + threadIdx.x;
    if (i >= 16 * BATCH * NFEAT) return;
    int part = i / (BATCH * NFEAT);
    int r = i - part * (BATCH * NFEAT);
    int b = r / NFEAT, f = r - b * NFEAT;
    decp[i] = (part == 0)
        ? (src[b * (LAGS * NFEAT) + (LAGS - 1) * NFEAT + f] - fc4_b[f])
        : 0.f;
}

__global__ void reset_bar() { g_bar = 0; }

// ---------------------------------------------------------------------------
// GEMM + cell device function.
// DEC_L0: k-tile 0 of A assembled in SMEM from decx partial sums (+fc4_b).
// FC:     epilogue emits fc4/fc1 partials (decoder layer 1).
// ---------------------------------------------------------------------------
#define ROW_B    96
#define A_BYTES  (64 * ROW_B)
#define STAGE_B  (A_BYTES + 128 * ROW_B)   // 18432
#define DYN_SMEM (4 * STAGE_B)             // 73728

template <int IN_DIM, bool DEC_L0, bool FC>
__device__ __forceinline__
void gemm_cell(char* smem, int bm, int bn,
               const __half* __restrict__ xA, int xs,
               const __half* __restrict__ hA,
               const __half* __restrict__ Wpk,
               const float* __restrict__ bs,
               float* __restrict__ cst,
               __half* __restrict__ h_out,
               const float* __restrict__ decp_in,   // DEC_L0
               const float* __restrict__ fc4_b,     // DEC_L0
               float* __restrict__ decp_out,        // FC
               float* __restrict__ fc1p_out,        // FC
               const float* __restrict__ fc4w,      // FC
               const float* __restrict__ fc1w)      // FC
{
    constexpr int K = IN_DIM + HIDDEN;
    constexpr int T = K / 32;

    const int tid  = threadIdx.x;
    const int w    = tid >> 5, lane = tid & 31;
    const int g    = lane >> 2, tg = lane & 3;
    const int wm0  = (w >> 2) * 32;
    const int wn0  = (w & 3) * 32;

    // ---- DEC_L0: assemble k-tile-0 A (decx) in SMEM stage 0 ----
    if (DEC_L0) {
        int row = tid >> 2, c = tid & 3;         // 64 rows x 4 chunks
        int gb  = bm * 64 + row;
        const float* dp = decp_in + gb * 32 + c * 8;
        float v[8];
#pragma unroll
        for (int u = 0; u < 8; ++u) v[u] = fc4_b[c * 8 + u];
#pragma unroll
        for (int p = 0; p < 16; ++p) {
            float4 a0 = *(const float4*)(dp + p * (BATCH * 32));
            float4 a1 = *(const float4*)(dp + p * (BATCH * 32) + 4);
            v[0] += a0.x; v[1] += a0.y; v[2] += a0.z; v[3] += a0.w;
            v[4] += a1.x; v[5] += a1.y; v[6] += a1.z; v[7] += a1.w;
        }
        __half2 h0 = __floats2half2_rn(v[0], v[1]);
        __half2 h1 = __floats2half2_rn(v[2], v[3]);
        __half2 h2 = __floats2half2_rn(v[4], v[5]);
        __half2 h3 = __floats2half2_rn(v[6], v[7]);
        uint4 pk = make_uint4(*(uint32_t*)&h0, *(uint32_t*)&h1,
                              *(uint32_t*)&h2, *(uint32_t*)&h3);
        *(uint4*)(smem + row * ROW_B + ((row >> 2) & 1) * 16 + c * 16) = pk;
    }

    auto issue = [&](int t) {
        const int s = t & 3;
        char* aB = smem + s * STAGE_B;
        char* bB = aB + A_BYTES;
        const int k0 = t * 32;
        if (!(DEC_L0 && t == 0)) {
            const __half* sA;
            int stride;
            if (k0 < IN_DIM) { sA = xA + k0;            stride = xs;     }
            else             { sA = hA + (k0 - IN_DIM); stride = HIDDEN; }
            int row = tid >> 2, c = tid & 3;     // A: 64 rows x 4 chunks
            cpa16(smem_u32(aB + row * ROW_B + ((row >> 2) & 1) * 16 + c * 16),
                  sA + (bm * 64 + row) * stride + c * 8);
        }
#pragma unroll
        for (int p = 0; p < 2; ++p) {            // B: 128 rows x 4 chunks
            int i   = tid + p * 256;
            int row = i >> 2, c = i & 3;
            cpa16(smem_u32(bB + row * ROW_B + ((row >> 2) & 1) * 16 + c * 16),
                  Wpk + (bn * 128 + row) * K + k0 + c * 8);
        }
        cpa_commit();
    };

    float acc[2][4][4];
#pragma unroll
    for (int mf = 0; mf < 2; ++mf)
#pragma unroll
        for (int nf = 0; nf < 4; ++nf)
#pragma unroll
            for (int q = 0; q < 4; ++q) acc[mf][nf][q] = 0.f;

    issue(0); issue(1); issue(2);

    for (int t = 0; t < T; ++t) {
        if (t < T - 2) asm volatile("cp.async.wait_group 2;" ::: "memory");
        else           asm volatile("cp.async.wait_group 0;" ::: "memory");
        __syncthreads();
        if (t + 3 < T) issue(t + 3);

        const int s = t & 3;
        const char* As = smem + s * STAGE_B;
        const char* Bs = As + A_BYTES;

#pragma unroll
        for (int ks = 0; ks < 2; ++ks) {
            const int kb = ks * 32 + 4 * tg;
            uint32_t a[2][4];
#pragma unroll
            for (int mf = 0; mf < 2; ++mf) {
                const int r0 = wm0 + mf * 16 + g;
                const int r1 = r0 + 8;
                const char* p0 = As + r0 * ROW_B + ((r0 >> 2) & 1) * 16 + kb;
                const char* p1 = As + r1 * ROW_B + ((r1 >> 2) & 1) * 16 + kb;
                a[mf][0] = *(const uint32_t*)p0;
                a[mf][1] = *(const uint32_t*)p1;
                a[mf][2] = *(const uint32_t*)(p0 + 16);
                a[mf][3] = *(const uint32_t*)(p1 + 16);
            }
#pragma unroll
            for (int nf = 0; nf < 4; ++nf) {
                const int nr = wn0 + nf * 8 + g;
                const char* pb = Bs + nr * ROW_B + ((nr >> 2) & 1) * 16 + kb;
                uint32_t b0 = *(const uint32_t*)pb;
                uint32_t b1 = *(const uint32_t*)(pb + 16);
                mma_f16(acc[0][nf], a[0], b0, b1);
                mma_f16(acc[1][nf], a[1], b0, b1);
            }
        }
    }

    // ---- epilogue ----
    __syncthreads();
    float* zs = (float*)smem;                     // [64][132]
    float* s_fcw = (float*)(smem + 40960);        // fc4 32x32 + fc1 32
#pragma unroll
    for (int mf = 0; mf < 2; ++mf)
#pragma unroll
        for (int nf = 0; nf < 4; ++nf) {
            int r = wm0 + mf * 16 + g;
            int c = wn0 + nf * 8 + 2 * tg;
            *(float2*)&zs[r * 132 + c]       = make_float2(acc[mf][nf][0], acc[mf][nf][1]);
            *(float2*)&zs[(r + 8) * 132 + c] = make_float2(acc[mf][nf][2], acc[mf][nf][3]);
        }
    if (FC) {
#pragma unroll
        for (int i = tid; i < 32 * 32; i += 256) {
            int f = i >> 5, jl = i & 31;
            s_fcw[i] = fc4w[f * HIDDEN + bn * 32 + jl];
        }
        if (tid < 32) s_fcw[1024 + tid] = fc1w[bn * 32 + tid];
    }
    __syncthreads();

#pragma unroll
    for (int p = 0; p < 8; ++p) {
        int idx = tid + p * 256;
        int bl = idx >> 5, jl = idx & 31;
        int b  = bm * 64 + bl;
        int j  = bn * 32 + jl;
        float4 z4 = *(float4*)&zs[bl * 132 + jl * 4];
        float4 b4 = *(const float4*)&bs[(bn * 32 + jl) * 4];
        float zi = z4.x + b4.x;
        float zf = z4.y + b4.y;
        float zg = z4.z + b4.z;
        float zo = z4.w + b4.w;
        float cn = fsigmoid(zf) * cst[b * HIDDEN + j] + fsigmoid(zi) * ftanh(zg);
        cst[b * HIDDEN + j] = cn;
        float hv = fsigmoid(zo) * ftanh(cn);
        h_out[b * HIDDEN + j] = __float2half_rn(hv);

        if (FC) {
            float keep = 0.f;
#pragma unroll
            for (int f = 0; f < 32; ++f) {
                float v = hv * s_fcw[f * 32 + jl];
                v += __shfl_xor_sync(0xffffffffu, v, 16);
                v += __shfl_xor_sync(0xffffffffu, v, 8);
                v += __shfl_xor_sync(0xffffffffu, v, 4);
                v += __shfl_xor_sync(0xffffffffu, v, 2);
                v += __shfl_xor_sync(0xffffffffu, v, 1);
                if (jl == f) keep = v;
            }
            decp_out[(bn * BATCH + b) * 32 + jl] = keep;
            float u = hv * s_fcw[1024 + jl];
            u += __shfl_xor_sync(0xffffffffu, u, 16);
            u += __shfl_xor_sync(0xffffffffu, u, 8);
            u += __shfl_xor_sync(0xffffffffu, u, 4);
            u += __shfl_xor_sync(0xffffffffu, u, 2);
            u += __shfl_xor_sync(0xffffffffu, u, 1);
            if (jl == 0) fc1p_out[bn * BATCH + b] = u;
        }
    }
    __syncthreads();
}

// ---------------------------------------------------------------------------
// Persistent kernel
// ---------------------------------------------------------------------------
__global__ __launch_bounds__(256, 1)
void lstm_persistent(const __half* __restrict__ xh,
                     const float* __restrict__ fc1_w, const float* __restrict__ fc1_b,
                     const float* __restrict__ fc4_w, const float* __restrict__ fc4_b,
                     float* __restrict__ out)
{
    extern __shared__ char smem[];
    unsigned char* S = g_scratch;

    const __half* WP0 = (const __half*)(S + OFF_WP0);
    const __half* WP1 = (const __half*)(S + OFF_WP1);
    const __half* WP2 = (const __half*)(S + OFF_WP2);
    const __half* WP3 = (const __half*)(S + OFF_WP3);
    const float*  BS  = (const float*)(S + OFF_BS);
    __half* Hst  = (__half*)(S + OFF_H);
    float*  Cst  = (float*)(S + OFF_C);
    float*  decp = (float*)(S + OFF_DECP);
    float*  fc1p = (float*)(S + OFF_FC1P);

    const int BH = BATCH * HIDDEN;
    __half* h0b[2] = {Hst + 0 * BH, Hst + 1 * BH};
    __half* h1b[2] = {Hst + 2 * BH, Hst + 3 * BH};
    float*  c0 = Cst;
    float*  c1 = Cst + BH;

    const int cta = blockIdx.x;
    const int bm = cta >> 4;     // 0..7
    const int bn = cta & 15;     // 0..15
    const int tid = threadIdx.x;

    unsigned int tgt = 0;

    // ---- encoder: waves 0..96 ----
    for (int w = 0; w <= LAGS; ++w) {
        if (w < LAGS)
            gemm_cell<NFEAT, false, false>(smem, bm, bn,
                xh + (size_t)w * BATCH * NFEAT, NFEAT, h0b[w & 1],
                WP0, BS + 0 * NGATE, c0, h0b[(w + 1) & 1],
                nullptr, nullptr, nullptr, nullptr, nullptr, nullptr);
        if (w >= 1)
            gemm_cell<HIDDEN, false, false>(smem, bm, bn,
                h0b[w & 1], HIDDEN, h1b[(w - 1) & 1],
                WP1, BS + 1 * NGATE, c1, h1b[w & 1],
                nullptr, nullptr, nullptr, nullptr, nullptr, nullptr);
        tgt += GRID_CTAS;
        grid_sync(tgt);
    }

    // ---- decoder: 24 steps x 2 waves ----
    for (int tt = 0; tt < HORIZONS; ++tt) {
        const int t = LAGS + tt;

        // wave A: write out[.,tt-1] (bn==0) then layer0
        if (bn == 0 && tt >= 1 && tid < 64) {
            int b = bm * 64 + tid;
            float s = fc1_b[0];
#pragma unroll
            for (int p = 0; p < 16; ++p) s += fc1p[p * BATCH + b];
            out[b * HORIZONS + (tt - 1)] = s;
        }
        gemm_cell<NFEAT, true, false>(smem, bm, bn,
            nullptr, 0, h0b[t & 1],
            WP2, BS + 2 * NGATE, c0, h0b[(t + 1) & 1],
            decp, fc4_b, nullptr, nullptr, nullptr, nullptr);
        tgt += GRID_CTAS;
        grid_sync(tgt);

        // wave B: layer1 + fc partials
        gemm_cell<HIDDEN, false, true>(smem, bm, bn,
            h0b[(t + 1) & 1], HIDDEN, h1b[t & 1],
            WP3, BS + 3 * NGATE, c1, h1b[(t + 1) & 1],
            nullptr, nullptr, decp, fc1p, fc4_w, fc1_w);
        tgt += GRID_CTAS;
        grid_sync(tgt);
    }

    // final: out[.,23]
    if (bn == 0 && tid < 64) {
        int b = bm * 64 + tid;
        float s = fc1_b[0];
#pragma unroll
        for (int p = 0; p < 16; ++p) s += fc1p[p * BATCH + b];
        out[b * HORIZONS + (HORIZONS - 1)] = s;
    }
}

// ---------------------------------------------------------------------------
extern "C" void kernel_launch(void* const* d_in, const int* in_sizes, int n_in,
                              void* d_out, int out_size)
{
    const int wb = (in_sizes[2] == 1) ? 3 : 2;

    const float* src = (const float*)d_in[0];
    const float* W[16];
    for (int i = 0; i < 16; i++) W[i] = (const float*)d_in[wb + i];
    const float* fc1_w = (const float*)d_in[wb + 16];
    const float* fc1_b = (const float*)d_in[wb + 17];
    const float* fc4_w = (const float*)d_in[wb + 18];
    const float* fc4_b = (const float*)d_in[wb + 19];
    float* out = (float*)d_out;

    unsigned char* S = nullptr;
    cudaGetSymbolAddress((void**)&S, g_scratch);

    __half* WP[4] = {(__half*)(S + OFF_WP0), (__half*)(S + OFF_WP1),
                     (__half*)(S + OFF_WP2), (__half*)(S + OFF_WP3)};
    float*  BS   = (float*)(S + OFF_BS);
    __half* Hst  = (__half*)(S + OFF_H);
    float*  Cst  = (float*)(S + OFF_C);
    __half* xh   = (__half*)(S + OFF_XH);
    float*  decp = (float*)(S + OFF_DECP);

    static bool attr_set = false;
    if (!attr_set) {
        cudaFuncSetAttribute(lstm_persistent,
                             cudaFuncAttributeMaxDynamicSharedMemorySize, DYN_SMEM);
        attr_set = true;
    }

    const int in_dims[4]  = {NFEAT, HIDDEN, NFEAT, HIDDEN};
    const int k_tot[4]    = {NFEAT + HIDDEN, 2 * HIDDEN, NFEAT + HIDDEN, 2 * HIDDEN};
    const int wp_elems[4] = {544 * 2048, 1024 * 2048, 544 * 2048, 1024 * 2048};

    for (int l = 0; l < 4; l++) {
        pack_weights<<<(wp_elems[l] + 255) / 256, 256>>>(W[l * 4 + 0], W[l * 4 + 1],
                                                         in_dims[l], k_tot[l], WP[l], wp_elems[l]);
        pack_bias<<<(NGATE + 255) / 256, 256>>>(W[l * 4 + 2], W[l * 4 + 3], BS + l * NGATE);
    }

    convert_src<<<(LAGS * BATCH * NFEAT + 255) / 256, 256>>>(src, xh);
    zero_h<<<(2 * 2 * BATCH * HIDDEN + 255) / 256, 256>>>(Hst, 2 * 2 * BATCH * HIDDEN);
    zero_f<<<(2 * BATCH * HIDDEN + 255) / 256, 256>>>(Cst, 2 * BATCH * HIDDEN);
    init_decp<<<(16 * BATCH * NFEAT + 255) / 256, 256>>>(src, fc4_b, decp);
    reset_bar<<<1, 1>>>();

    lstm_persistent<<<GRID_CTAS, 256, DYN_SMEM>>>(xh, fc1_w, fc1_b, fc4_w, fc4_b, out);
}

// round 6
// speedup vs baseline: 1.2718x; 1.2718x over previous
#include <cuda_runtime.h>
#include <cuda_fp16.h>
#include <cstdint>

// ---------------------------------------------------------------------------
// LSTM Seq2Seq on GB300 — fp16 mma.sync + ldmatrix, 64x64 tiles, 256 CTAs,
// 2 CTAs/SM. Separate launches per (step,layer); single setup kernel ordered
// so ncu (-s 5) captures the layer-1 GEMM.
// ---------------------------------------------------------------------------

#define HIDDEN   512
#define BATCH    512
#define NFEAT    32
#define LAGS     96
#define HORIZONS 24
#define NGATE    2048

// ---- byte-based scratch layout ----
#define OFF_WP0   0u
#define SZ_WP0B   (544u * 2048u * 2u)
#define OFF_WP1   (OFF_WP0 + SZ_WP0B)
#define SZ_WP1B   (1024u * 2048u * 2u)
#define OFF_WP2   (OFF_WP1 + SZ_WP1B)
#define OFF_WP3   (OFF_WP2 + SZ_WP0B)
#define OFF_BS    (OFF_WP3 + SZ_WP1B)                  // float[4*2048]
#define OFF_H     (OFF_BS + 4u * 2048u * 4u)           // half[2*2*512*512]
#define OFF_C     (OFF_H + 2u * 2u * 512u * 512u * 2u) // float[2*512*512]
#define OFF_XH    (OFF_C + 2u * 512u * 512u * 4u)      // half[96*512*32]
#define OFF_DECX  (OFF_XH + 96u * 512u * 32u * 2u)     // half[512*32]
#define SCRATCH_BYTES (OFF_DECX + 512u * 32u * 2u)

__device__ __align__(1024) unsigned char g_scratch[SCRATCH_BYTES];

// ---------------------------------------------------------------------------
__device__ __forceinline__ uint32_t smem_u32(const void* p) {
    return (uint32_t)__cvta_generic_to_shared(p);
}
__device__ __forceinline__ void cpa16(uint32_t dst, const void* src) {
    asm volatile("cp.async.cg.shared.global [%0], [%1], 16;" :: "r"(dst), "l"(src));
}
__device__ __forceinline__ void cpa_commit() {
    asm volatile("cp.async.commit_group;" ::: "memory");
}
__device__ __forceinline__ void ldsm4(uint32_t* r, uint32_t addr) {
    asm volatile("ldmatrix.sync.aligned.m8n8.x4.shared.b16 {%0,%1,%2,%3}, [%4];"
                 : "=r"(r[0]), "=r"(r[1]), "=r"(r[2]), "=r"(r[3]) : "r"(addr));
}
__device__ __forceinline__ void mma_f16(float* d, const uint32_t* a,
                                        uint32_t b0, uint32_t b1) {
    asm volatile(
        "mma.sync.aligned.m16n8k16.row.col.f32.f16.f16.f32 "
        "{%0,%1,%2,%3},{%4,%5,%6,%7},{%8,%9},{%0,%1,%2,%3};"
        : "+f"(d[0]), "+f"(d[1]), "+f"(d[2]), "+f"(d[3])
        : "r"(a[0]), "r"(a[1]), "r"(a[2]), "r"(a[3]), "r"(b0), "r"(b1));
}
__device__ __forceinline__ float fsigmoid(float x) { return 1.f / (1.f + __expf(-x)); }
__device__ __forceinline__ float ftanh(float x)    { return 2.f / (1.f + __expf(-2.f * x)) - 1.f; }

// ---------------------------------------------------------------------------
// Setup: ALL packing/conversion/zeroing in one kernel (launch #1)
// ---------------------------------------------------------------------------
struct WPtrs { const float* w[16]; };

__global__ void setup_all(const float* __restrict__ src, WPtrs wp)
{
    unsigned char* S = g_scratch;
    __half* WP[4] = {(__half*)(S + OFF_WP0), (__half*)(S + OFF_WP1),
                     (__half*)(S + OFF_WP2), (__half*)(S + OFF_WP3)};
    float*  BS  = (float*)(S + OFF_BS);
    __half* Hst = (__half*)(S + OFF_H);
    float*  Cst = (float*)(S + OFF_C);
    __half* xh  = (__half*)(S + OFF_XH);

    const int gs   = gridDim.x * blockDim.x;
    const int tid0 = blockIdx.x * blockDim.x + threadIdx.x;
    const int in_dims[4] = {NFEAT, HIDDEN, NFEAT, HIDDEN};
    const int ktot[4]    = {NFEAT + HIDDEN, 2 * HIDDEN, NFEAT + HIDDEN, 2 * HIDDEN};

#pragma unroll
    for (int l = 0; l < 4; ++l) {
        const float* Wih = wp.w[l * 4 + 0];
        const float* Whh = wp.w[l * 4 + 1];
        const int Ktot = ktot[l], total = Ktot * NGATE;
        for (int idx = tid0; idx < total; idx += gs) {
            int n = idx / Ktot, k = idx - n * Ktot;
            int j = n >> 2, g = n & 3;
            float v = (k < in_dims[l]) ? Wih[(g * HIDDEN + j) * in_dims[l] + k]
                                       : Whh[(g * HIDDEN + j) * HIDDEN + (k - in_dims[l])];
            WP[l][idx] = __float2half_rn(v);
        }
        const float* bih = wp.w[l * 4 + 2];
        const float* bhh = wp.w[l * 4 + 3];
        for (int n = tid0; n < NGATE; n += gs) {
            int j = n >> 2, g = n & 3;
            BS[l * NGATE + n] = bih[g * HIDDEN + j] + bhh[g * HIDDEN + j];
        }
    }
    for (int i = tid0; i < LAGS * BATCH * NFEAT; i += gs) {
        int t = i / (BATCH * NFEAT);
        int r = i - t * (BATCH * NFEAT);
        int b = r / NFEAT, f = r - b * NFEAT;
        xh[i] = __float2half_rn(src[b * (LAGS * NFEAT) + t * NFEAT + f]);
    }
    for (int i = tid0; i < 2 * 2 * BATCH * HIDDEN; i += gs) Hst[i] = __half(0.f);
    for (int i = tid0; i < 2 * BATCH * HIDDEN; i += gs)     Cst[i] = 0.f;
}

// launch #2 (also spaces ncu -s 5 onto the layer-1 GEMM)
__global__ void init_decx(const float* __restrict__ src, __half* __restrict__ decx)
{
    int i = blockIdx.x * blockDim.x + threadIdx.x;
    if (i >= BATCH * NFEAT) return;
    int b = i / NFEAT, f = i - b * NFEAT;
    decx[i] = __float2half_rn(src[b * (LAGS * NFEAT) + (LAGS - 1) * NFEAT + f]);
}

// ---------------------------------------------------------------------------
// Fused fp16 GEMM + LSTM cell. CTA tile 64(m)x64(n), BK=32, 128 threads,
// 4 warps of 32x32 (2m x 2n), 4-stage cp.async, ldmatrix.x4 fragment loads.
// grid(32, 8) = 256 CTAs -> ~2 CTAs/SM.
// SMEM row layout: row r chunk c(16B) at r*96 + ((r>>2)&1)*16 + c*16.
// ---------------------------------------------------------------------------
#define ROW_B    96
#define A_BYTES  (64 * ROW_B)       // 6144
#define STAGE_B  (2 * A_BYTES)      // 12288
#define DYN_SMEM (4 * STAGE_B)      // 49152

template <int IN_DIM>
__global__ __launch_bounds__(128, 2)
void lstm_step_mma(const __half* __restrict__ xA, int xs,
                   const __half* __restrict__ hA,
                   const __half* __restrict__ Wpk,
                   const float* __restrict__ bs,
                   float* __restrict__ cst,
                   __half* __restrict__ h_out)
{
    constexpr int K = IN_DIM + HIDDEN;
    constexpr int T = K / 32;

    extern __shared__ char smem[];
    const int tid  = threadIdx.x;
    const int bn   = blockIdx.x, bm = blockIdx.y;
    const int w    = tid >> 5, lane = tid & 31;
    const int g    = lane >> 2, tg = lane & 3;
    const int wm0  = (w >> 1) * 32;
    const int wn0  = (w & 1) * 32;
    const uint32_t sb = smem_u32(smem);

    // per-lane ldmatrix base addresses (stage 0, ks 0)
    uint32_t aBase[2], bBase[2];
#pragma unroll
    for (int mf = 0; mf < 2; ++mf) {
        int r = wm0 + mf * 16 + (lane & 7) + ((lane >> 3) & 1) * 8;
        aBase[mf] = sb + r * ROW_B + ((r >> 2) & 1) * 16 + ((lane >> 4) & 1) * 16;
    }
#pragma unroll
    for (int p = 0; p < 2; ++p) {
        int n = wn0 + p * 16 + (lane & 7) + ((lane >> 4) & 1) * 8;
        bBase[p] = sb + A_BYTES + n * ROW_B + ((n >> 2) & 1) * 16 + ((lane >> 3) & 1) * 16;
    }

    auto issue = [&](int t) {
        const int s = t & 3;
        char* aB = smem + s * STAGE_B;
        char* bB = aB + A_BYTES;
        const int k0 = t * 32;
        const __half* sA;
        int stride;
        if (k0 < IN_DIM) { sA = xA + k0;            stride = xs;     }
        else             { sA = hA + (k0 - IN_DIM); stride = HIDDEN; }
#pragma unroll
        for (int p = 0; p < 2; ++p) {            // A: 64 rows x 4 chunks
            int i = tid + p * 128;
            int row = i >> 2, c = i & 3;
            cpa16(smem_u32(aB + row * ROW_B + ((row >> 2) & 1) * 16 + c * 16),
                  sA + (bm * 64 + row) * stride + c * 8);
        }
#pragma unroll
        for (int p = 0; p < 2; ++p) {            // B: 64 rows x 4 chunks
            int i = tid + p * 128;
            int row = i >> 2, c = i & 3;
            cpa16(smem_u32(bB + row * ROW_B + ((row >> 2) & 1) * 16 + c * 16),
                  Wpk + (bn * 64 + row) * K + k0 + c * 8);
        }
        cpa_commit();
    };

    float acc[2][4][4];
#pragma unroll
    for (int mf = 0; mf < 2; ++mf)
#pragma unroll
        for (int nf = 0; nf < 4; ++nf)
#pragma unroll
            for (int q = 0; q < 4; ++q) acc[mf][nf][q] = 0.f;

    issue(0); issue(1); issue(2);

    for (int t = 0; t < T; ++t) {
        if (t < T - 2) asm volatile("cp.async.wait_group 2;" ::: "memory");
        else           asm volatile("cp.async.wait_group 0;" ::: "memory");
        __syncthreads();
        if (t + 3 < T) issue(t + 3);

        const uint32_t soff = (uint32_t)(t & 3) * STAGE_B;
#pragma unroll
        for (int ks = 0; ks < 2; ++ks) {
            const uint32_t o = soff + ks * 32;
            uint32_t a0[4], a1[4], b0[4], b1[4];
            ldsm4(a0, aBase[0] + o);
            ldsm4(a1, aBase[1] + o);
            ldsm4(b0, bBase[0] + o);   // {b0(nf0), b1(nf0), b0(nf1), b1(nf1)}
            ldsm4(b1, bBase[1] + o);   // {b0(nf2), b1(nf2), b0(nf3), b1(nf3)}
            mma_f16(acc[0][0], a0, b0[0], b0[1]);
            mma_f16(acc[0][1], a0, b0[2], b0[3]);
            mma_f16(acc[0][2], a0, b1[0], b1[1]);
            mma_f16(acc[0][3], a0, b1[2], b1[3]);
            mma_f16(acc[1][0], a1, b0[0], b0[1]);
            mma_f16(acc[1][1], a1, b0[2], b0[3]);
            mma_f16(acc[1][2], a1, b1[0], b1[1]);
            mma_f16(acc[1][3], a1, b1[2], b1[3]);
        }
    }

    // ---- epilogue: accs -> SMEM z-tile [64][68] -> fused LSTM cell ----
    __syncthreads();
    float* zs = (float*)smem;
#pragma unroll
    for (int mf = 0; mf < 2; ++mf)
#pragma unroll
        for (int nf = 0; nf < 4; ++nf) {
            int r = wm0 + mf * 16 + g;
            int c = wn0 + nf * 8 + 2 * tg;
            *(float2*)&zs[r * 68 + c]       = make_float2(acc[mf][nf][0], acc[mf][nf][1]);
            *(float2*)&zs[(r + 8) * 68 + c] = make_float2(acc[mf][nf][2], acc[mf][nf][3]);
        }
    __syncthreads();

#pragma unroll
    for (int p = 0; p < 8; ++p) {
        int idx = tid + p * 128;                 // 1024 = 64 rows x 16 j
        int bl = idx >> 4, jl = idx & 15;
        int b  = bm * 64 + bl;
        int j  = bn * 16 + jl;
        float4 z4 = *(float4*)&zs[bl * 68 + jl * 4];
        float4 b4 = *(const float4*)&bs[(bn * 16 + jl) * 4];
        float zi = z4.x + b4.x;
        float zf = z4.y + b4.y;
        float zg = z4.z + b4.z;
        float zo = z4.w + b4.w;
        float cn = fsigmoid(zf) * cst[b * HIDDEN + j] + fsigmoid(zi) * ftanh(zg);
        cst[b * HIDDEN + j]   = cn;
        h_out[b * HIDDEN + j] = __float2half_rn(fsigmoid(zo) * ftanh(cn));
    }
}

// ---------------------------------------------------------------------------
// Decoder heads
// ---------------------------------------------------------------------------
__global__ __launch_bounds__(256)
void dec_fc(const __half* __restrict__ h1,
            const float* __restrict__ fc1_w, const float* __restrict__ fc1_b,
            const float* __restrict__ fc4_w, const float* __restrict__ fc4_b,
            float* __restrict__ out, int t, __half* __restrict__ decx)
{
    __shared__ float sh[HIDDEN];
    const int b = blockIdx.x;
    for (int i = threadIdx.x; i < HIDDEN; i += blockDim.x)
        sh[i] = __half2float(h1[b * HIDDEN + i]);
    __syncthreads();

    const int warp = threadIdx.x >> 5;
    const int lane = threadIdx.x & 31;
    for (int o = warp; o < 1 + NFEAT; o += 8) {
        const float* w = (o == 0) ? fc1_w : (fc4_w + (o - 1) * HIDDEN);
        float s = 0.f;
#pragma unroll 4
        for (int k = lane; k < HIDDEN; k += 32) s += sh[k] * w[k];
#pragma unroll
        for (int off = 16; off; off >>= 1) s += __shfl_down_sync(0xffffffffu, s, off);
        if (lane == 0) {
            if (o == 0) out[b * HORIZONS + t] = s + fc1_b[0];
            else        decx[b * NFEAT + (o - 1)] = __float2half_rn(s + fc4_b[o - 1]);
        }
    }
}

// ---------------------------------------------------------------------------
extern "C" void kernel_launch(void* const* d_in, const int* in_sizes, int n_in,
                              void* d_out, int out_size)
{
    const int wb = (in_sizes[2] == 1) ? 3 : 2;

    const float* src = (const float*)d_in[0];
    WPtrs wp;
    for (int i = 0; i < 16; i++) wp.w[i] = (const float*)d_in[wb + i];
    const float* fc1_w = (const float*)d_in[wb + 16];
    const float* fc1_b = (const float*)d_in[wb + 17];
    const float* fc4_w = (const float*)d_in[wb + 18];
    const float* fc4_b = (const float*)d_in[wb + 19];
    float* out = (float*)d_out;

    unsigned char* S = nullptr;
    cudaGetSymbolAddress((void**)&S, g_scratch);

    __half* WP[4] = {(__half*)(S + OFF_WP0), (__half*)(S + OFF_WP1),
                     (__half*)(S + OFF_WP2), (__half*)(S + OFF_WP3)};
    float*  BS   = (float*)(S + OFF_BS);
    __half* Hst  = (__half*)(S + OFF_H);
    float*  Cst  = (float*)(S + OFF_C);
    __half* xh   = (__half*)(S + OFF_XH);
    __half* decx = (__half*)(S + OFF_DECX);

    cudaFuncSetAttribute(lstm_step_mma<NFEAT>,
                         cudaFuncAttributeMaxDynamicSharedMemorySize, DYN_SMEM);
    cudaFuncSetAttribute(lstm_step_mma<HIDDEN>,
                         cudaFuncAttributeMaxDynamicSharedMemorySize, DYN_SMEM);

    // launch #1: all setup. launch #2: init_decx. -> launch #6 = layer1 GEMM (ncu -s 5)
    setup_all<<<1024, 256>>>(src, wp);
    init_decx<<<(BATCH * NFEAT + 255) / 256, 256>>>(src, decx);

    dim3 grid(NGATE / 64, BATCH / 64);  // (32, 8) = 256 CTAs
    const int BH = BATCH * HIDDEN;

    for (int t = 0; t < LAGS; t++) {
        const __half* h0_in  = Hst + (0 * 2 + (t & 1)) * BH;
        __half*       h0_out = Hst + (0 * 2 + ((t + 1) & 1)) * BH;
        const __half* h1_in  = Hst + (2 + (t & 1)) * BH;
        __half*       h1_out = Hst + (2 + ((t + 1) & 1)) * BH;

        lstm_step_mma<NFEAT><<<grid, 128, DYN_SMEM>>>(xh + t * BATCH * NFEAT, NFEAT,
                                                      h0_in, WP[0], BS + 0 * NGATE,
                                                      Cst + 0 * BH, h0_out);
        lstm_step_mma<HIDDEN><<<grid, 128, DYN_SMEM>>>(h0_out, HIDDEN,
                                                       h1_in, WP[1], BS + 1 * NGATE,
                                                       Cst + 1 * BH, h1_out);
    }

    for (int tt = 0; tt < HORIZONS; tt++) {
        int t = LAGS + tt;
        const __half* h0_in  = Hst + (0 * 2 + (t & 1)) * BH;
        __half*       h0_out = Hst + (0 * 2 + ((t + 1) & 1)) * BH;
        const __half* h1_in  = Hst + (2 + (t & 1)) * BH;
        __half*       h1_out = Hst + (2 + ((t + 1) & 1)) * BH;

        lstm_step_mma<NFEAT><<<grid, 128, DYN_SMEM>>>(decx, NFEAT,
                                                      h0_in, WP[2], BS + 2 * NGATE,
                                                      Cst + 0 * BH, h0_out);
        lstm_step_mma<HIDDEN><<<grid, 128, DYN_SMEM>>>(h0_out, HIDDEN,
                                                       h1_in, WP[3], BS + 3 * NGATE,
                                                       Cst + 1 * BH, h1_out);
        dec_fc<<<BATCH, 256>>>(h1_out, fc1_w, fc1_b, fc4_w, fc4_b, out, tt, decx);
    }
}

// round 7
// speedup vs baseline: 1.3345x; 1.0492x over previous
#include <cuda_runtime.h>
#include <cuda_fp16.h>
#include <cstdint>

// ---------------------------------------------------------------------------
// LSTM Seq2Seq on GB300 — fp16 mma.sync + ldmatrix, 64x64 CTA tile,
// 256 threads (8 warps, warp tile 32x16), 256 CTAs, 2 CTAs/SM.
// Separate launches per (step,layer); setup ordered so ncu hits layer-1 GEMM.
// ---------------------------------------------------------------------------

#define HIDDEN   512
#define BATCH    512
#define NFEAT    32
#define LAGS     96
#define HORIZONS 24
#define NGATE    2048

// ---- byte-based scratch layout ----
#define OFF_WP0   0u
#define SZ_WP0B   (544u * 2048u * 2u)
#define OFF_WP1   (OFF_WP0 + SZ_WP0B)
#define SZ_WP1B   (1024u * 2048u * 2u)
#define OFF_WP2   (OFF_WP1 + SZ_WP1B)
#define OFF_WP3   (OFF_WP2 + SZ_WP0B)
#define OFF_BS    (OFF_WP3 + SZ_WP1B)                  // float[4*2048]
#define OFF_H     (OFF_BS + 4u * 2048u * 4u)           // half[2*2*512*512]
#define OFF_C     (OFF_H + 2u * 2u * 512u * 512u * 2u) // float[2*512*512]
#define OFF_XH    (OFF_C + 2u * 512u * 512u * 4u)      // half[96*512*32]
#define OFF_DECX  (OFF_XH + 96u * 512u * 32u * 2u)     // half[512*32]
#define SCRATCH_BYTES (OFF_DECX + 512u * 32u * 2u)

__device__ __align__(1024) unsigned char g_scratch[SCRATCH_BYTES];

// ---------------------------------------------------------------------------
__device__ __forceinline__ uint32_t smem_u32(const void* p) {
    return (uint32_t)__cvta_generic_to_shared(p);
}
__device__ __forceinline__ void cpa16(uint32_t dst, const void* src) {
    asm volatile("cp.async.cg.shared.global [%0], [%1], 16;" :: "r"(dst), "l"(src));
}
__device__ __forceinline__ void cpa_commit() {
    asm volatile("cp.async.commit_group;" ::: "memory");
}
__device__ __forceinline__ void ldsm4(uint32_t* r, uint32_t addr) {
    asm volatile("ldmatrix.sync.aligned.m8n8.x4.shared.b16 {%0,%1,%2,%3}, [%4];"
                 : "=r"(r[0]), "=r"(r[1]), "=r"(r[2]), "=r"(r[3]) : "r"(addr));
}
__device__ __forceinline__ void mma_f16(float* d, const uint32_t* a,
                                        uint32_t b0, uint32_t b1) {
    asm volatile(
        "mma.sync.aligned.m16n8k16.row.col.f32.f16.f16.f32 "
        "{%0,%1,%2,%3},{%4,%5,%6,%7},{%8,%9},{%0,%1,%2,%3};"
        : "+f"(d[0]), "+f"(d[1]), "+f"(d[2]), "+f"(d[3])
        : "r"(a[0]), "r"(a[1]), "r"(a[2]), "r"(a[3]), "r"(b0), "r"(b1));
}
__device__ __forceinline__ float fsigmoid(float x) { return 1.f / (1.f + __expf(-x)); }
__device__ __forceinline__ float ftanh(float x)    { return 2.f / (1.f + __expf(-2.f * x)) - 1.f; }

// ---------------------------------------------------------------------------
// Setup: ALL packing/conversion/zeroing in one kernel (launch #1)
// ---------------------------------------------------------------------------
struct WPtrs { const float* w[16]; };

__global__ void setup_all(const float* __restrict__ src, WPtrs wp)
{
    unsigned char* S = g_scratch;
    __half* WP[4] = {(__half*)(S + OFF_WP0), (__half*)(S + OFF_WP1),
                     (__half*)(S + OFF_WP2), (__half*)(S + OFF_WP3)};
    float*  BS  = (float*)(S + OFF_BS);
    __half* Hst = (__half*)(S + OFF_H);
    float*  Cst = (float*)(S + OFF_C);
    __half* xh  = (__half*)(S + OFF_XH);

    const int gs   = gridDim.x * blockDim.x;
    const int tid0 = blockIdx.x * blockDim.x + threadIdx.x;
    const int in_dims[4] = {NFEAT, HIDDEN, NFEAT, HIDDEN};
    const int ktot[4]    = {NFEAT + HIDDEN, 2 * HIDDEN, NFEAT + HIDDEN, 2 * HIDDEN};

#pragma unroll
    for (int l = 0; l < 4; ++l) {
        const float* Wih = wp.w[l * 4 + 0];
        const float* Whh = wp.w[l * 4 + 1];
        const int Ktot = ktot[l], total = Ktot * NGATE;
        for (int idx = tid0; idx < total; idx += gs) {
            int n = idx / Ktot, k = idx - n * Ktot;
            int j = n >> 2, g = n & 3;
            float v = (k < in_dims[l]) ? Wih[(g * HIDDEN + j) * in_dims[l] + k]
                                       : Whh[(g * HIDDEN + j) * HIDDEN + (k - in_dims[l])];
            WP[l][idx] = __float2half_rn(v);
        }
        const float* bih = wp.w[l * 4 + 2];
        const float* bhh = wp.w[l * 4 + 3];
        for (int n = tid0; n < NGATE; n += gs) {
            int j = n >> 2, g = n & 3;
            BS[l * NGATE + n] = bih[g * HIDDEN + j] + bhh[g * HIDDEN + j];
        }
    }
    for (int i = tid0; i < LAGS * BATCH * NFEAT; i += gs) {
        int t = i / (BATCH * NFEAT);
        int r = i - t * (BATCH * NFEAT);
        int b = r / NFEAT, f = r - b * NFEAT;
        xh[i] = __float2half_rn(src[b * (LAGS * NFEAT) + t * NFEAT + f]);
    }
    for (int i = tid0; i < 2 * 2 * BATCH * HIDDEN; i += gs) Hst[i] = __half(0.f);
    for (int i = tid0; i < 2 * BATCH * HIDDEN; i += gs)     Cst[i] = 0.f;
}

// launch #2
__global__ void init_decx(const float* __restrict__ src, __half* __restrict__ decx)
{
    int i = blockIdx.x * blockDim.x + threadIdx.x;
    if (i >= BATCH * NFEAT) return;
    int b = i / NFEAT, f = i - b * NFEAT;
    decx[i] = __float2half_rn(src[b * (LAGS * NFEAT) + (LAGS - 1) * NFEAT + f]);
}

// ---------------------------------------------------------------------------
// Fused fp16 GEMM + LSTM cell. CTA tile 64(m)x64(n), BK=32, 256 threads,
// 8 warps of 32x16 (2m x 4n), 4-stage cp.async, ldmatrix.x4 fragment loads.
// grid(32, 8) = 256 CTAs -> 2 CTAs/SM (single wave on 148 SMs).
// SMEM row layout: row r chunk c(16B) at r*96 + ((r>>2)&1)*16 + c*16.
// ---------------------------------------------------------------------------
#define ROW_B    96
#define A_BYTES  (64 * ROW_B)       // 6144
#define STAGE_B  (2 * A_BYTES)      // 12288
#define DYN_SMEM (4 * STAGE_B)      // 49152

template <int IN_DIM>
__global__ __launch_bounds__(256, 2)
void lstm_step_mma(const __half* __restrict__ xA, int xs,
                   const __half* __restrict__ hA,
                   const __half* __restrict__ Wpk,
                   const float* __restrict__ bs,
                   float* __restrict__ cst,
                   __half* __restrict__ h_out)
{
    constexpr int K = IN_DIM + HIDDEN;
    constexpr int T = K / 32;

    extern __shared__ char smem[];
    const int tid  = threadIdx.x;
    const int bn   = blockIdx.x, bm = blockIdx.y;
    const int w    = tid >> 5, lane = tid & 31;
    const int g    = lane >> 2, tg = lane & 3;
    const int wm0  = (w >> 2) * 32;     // 0 / 32
    const int wn0  = (w & 3) * 16;      // 0 / 16 / 32 / 48
    const uint32_t sb = smem_u32(smem);

    // per-lane ldmatrix base addresses (stage 0, ks 0)
    uint32_t aBase[2], bBase;
#pragma unroll
    for (int mf = 0; mf < 2; ++mf) {
        int r = wm0 + mf * 16 + (lane & 7) + ((lane >> 3) & 1) * 8;
        aBase[mf] = sb + r * ROW_B + ((r >> 2) & 1) * 16 + ((lane >> 4) & 1) * 16;
    }
    {
        int n = wn0 + (lane & 7) + ((lane >> 4) & 1) * 8;
        bBase = sb + A_BYTES + n * ROW_B + ((n >> 2) & 1) * 16 + ((lane >> 3) & 1) * 16;
    }

    auto issue = [&](int t) {
        const int s = t & 3;
        char* aB = smem + s * STAGE_B;
        char* bB = aB + A_BYTES;
        const int k0 = t * 32;
        const __half* sA;
        int stride;
        if (k0 < IN_DIM) { sA = xA + k0;            stride = xs;     }
        else             { sA = hA + (k0 - IN_DIM); stride = HIDDEN; }
        {   // A: 64 rows x 4 chunks = 256 -> 1/thread
            int row = tid >> 2, c = tid & 3;
            cpa16(smem_u32(aB + row * ROW_B + ((row >> 2) & 1) * 16 + c * 16),
                  sA + (bm * 64 + row) * stride + c * 8);
        }
        {   // B: 64 rows x 4 chunks = 256 -> 1/thread
            int row = tid >> 2, c = tid & 3;
            cpa16(smem_u32(bB + row * ROW_B + ((row >> 2) & 1) * 16 + c * 16),
                  Wpk + (bn * 64 + row) * K + k0 + c * 8);
        }
        cpa_commit();
    };

    float acc[2][2][4];
#pragma unroll
    for (int mf = 0; mf < 2; ++mf)
#pragma unroll
        for (int nf = 0; nf < 2; ++nf)
#pragma unroll
            for (int q = 0; q < 4; ++q) acc[mf][nf][q] = 0.f;

    issue(0); issue(1); issue(2);

    for (int t = 0; t < T; ++t) {
        if (t < T - 2) asm volatile("cp.async.wait_group 2;" ::: "memory");
        else           asm volatile("cp.async.wait_group 0;" ::: "memory");
        __syncthreads();
        if (t + 3 < T) issue(t + 3);

        const uint32_t soff = (uint32_t)(t & 3) * STAGE_B;
#pragma unroll
        for (int ks = 0; ks < 2; ++ks) {
            const uint32_t o = soff + ks * 32;
            uint32_t a0[4], a1[4], b[4];
            ldsm4(a0, aBase[0] + o);
            ldsm4(a1, aBase[1] + o);
            ldsm4(b,  bBase + o);      // {b0(nf0), b1(nf0), b0(nf1), b1(nf1)}
            mma_f16(acc[0][0], a0, b[0], b[1]);
            mma_f16(acc[0][1], a0, b[2], b[3]);
            mma_f16(acc[1][0], a1, b[0], b[1]);
            mma_f16(acc[1][1], a1, b[2], b[3]);
        }
    }

    // ---- epilogue: accs -> SMEM z-tile [64][68] -> fused LSTM cell ----
    __syncthreads();
    float* zs = (float*)smem;
#pragma unroll
    for (int mf = 0; mf < 2; ++mf)
#pragma unroll
        for (int nf = 0; nf < 2; ++nf) {
            int r = wm0 + mf * 16 + g;
            int c = wn0 + nf * 8 + 2 * tg;
            *(float2*)&zs[r * 68 + c]       = make_float2(acc[mf][nf][0], acc[mf][nf][1]);
            *(float2*)&zs[(r + 8) * 68 + c] = make_float2(acc[mf][nf][2], acc[mf][nf][3]);
        }
    __syncthreads();

#pragma unroll
    for (int p = 0; p < 4; ++p) {
        int idx = tid + p * 256;                 // 1024 = 64 rows x 16 j
        int bl = idx >> 4, jl = idx & 15;
        int b  = bm * 64 + bl;
        int j  = bn * 16 + jl;
        float4 z4 = *(float4*)&zs[bl * 68 + jl * 4];
        float4 b4 = *(const float4*)&bs[(bn * 16 + jl) * 4];
        float zi = z4.x + b4.x;
        float zf = z4.y + b4.y;
        float zg = z4.z + b4.z;
        float zo = z4.w + b4.w;
        float cn = fsigmoid(zf) * cst[b * HIDDEN + j] + fsigmoid(zi) * ftanh(zg);
        cst[b * HIDDEN + j]   = cn;
        h_out[b * HIDDEN + j] = __float2half_rn(fsigmoid(zo) * ftanh(cn));
    }
}

// ---------------------------------------------------------------------------
// Decoder heads
// ---------------------------------------------------------------------------
__global__ __launch_bounds__(256)
void dec_fc(const __half* __restrict__ h1,
            const float* __restrict__ fc1_w, const float* __restrict__ fc1_b,
            const float* __restrict__ fc4_w, const float* __restrict__ fc4_b,
            float* __restrict__ out, int t, __half* __restrict__ decx)
{
    __shared__ float sh[HIDDEN];
    const int b = blockIdx.x;
    for (int i = threadIdx.x; i < HIDDEN; i += blockDim.x)
        sh[i] = __half2float(h1[b * HIDDEN + i]);
    __syncthreads();

    const int warp = threadIdx.x >> 5;
    const int lane = threadIdx.x & 31;
    for (int o = warp; o < 1 + NFEAT; o += 8) {
        const float* w = (o == 0) ? fc1_w : (fc4_w + (o - 1) * HIDDEN);
        float s = 0.f;
#pragma unroll 4
        for (int k = lane; k < HIDDEN; k += 32) s += sh[k] * w[k];
#pragma unroll
        for (int off = 16; off; off >>= 1) s += __shfl_down_sync(0xffffffffu, s, off);
        if (lane == 0) {
            if (o == 0) out[b * HORIZONS + t] = s + fc1_b[0];
            else        decx[b * NFEAT + (o - 1)] = __float2half_rn(s + fc4_b[o - 1]);
        }
    }
}

// ---------------------------------------------------------------------------
extern "C" void kernel_launch(void* const* d_in, const int* in_sizes, int n_in,
                              void* d_out, int out_size)
{
    const int wb = (in_sizes[2] == 1) ? 3 : 2;

    const float* src = (const float*)d_in[0];
    WPtrs wp;
    for (int i = 0; i < 16; i++) wp.w[i] = (const float*)d_in[wb + i];
    const float* fc1_w = (const float*)d_in[wb + 16];
    const float* fc1_b = (const float*)d_in[wb + 17];
    const float* fc4_w = (const float*)d_in[wb + 18];
    const float* fc4_b = (const float*)d_in[wb + 19];
    float* out = (float*)d_out;

    unsigned char* S = nullptr;
    cudaGetSymbolAddress((void**)&S, g_scratch);

    __half* WP[4] = {(__half*)(S + OFF_WP0), (__half*)(S + OFF_WP1),
                     (__half*)(S + OFF_WP2), (__half*)(S + OFF_WP3)};
    float*  BS   = (float*)(S + OFF_BS);
    __half* Hst  = (__half*)(S + OFF_H);
    float*  Cst  = (float*)(S + OFF_C);
    __half* xh   = (__half*)(S + OFF_XH);
    __half* decx = (__half*)(S + OFF_DECX);

    cudaFuncSetAttribute(lstm_step_mma<NFEAT>,
                         cudaFuncAttributeMaxDynamicSharedMemorySize, DYN_SMEM);
    cudaFuncSetAttribute(lstm_step_mma<HIDDEN>,
                         cudaFuncAttributeMaxDynamicSharedMemorySize, DYN_SMEM);

    // launch #1: all setup. launch #2: init_decx. -> launch #6 = layer1 GEMM (ncu -s 5)
    setup_all<<<1024, 256>>>(src, wp);
    init_decx<<<(BATCH * NFEAT + 255) / 256, 256>>>(src, decx);

    dim3 grid(NGATE / 64, BATCH / 64);  // (32, 8) = 256 CTAs
    const int BH = BATCH * HIDDEN;

    for (int t = 0; t < LAGS; t++) {
        const __half* h0_in  = Hst + (0 * 2 + (t & 1)) * BH;
        __half*       h0_out = Hst + (0 * 2 + ((t + 1) & 1)) * BH;
        const __half* h1_in  = Hst + (2 + (t & 1)) * BH;
        __half*       h1_out = Hst + (2 + ((t + 1) & 1)) * BH;

        lstm_step_mma<NFEAT><<<grid, 256, DYN_SMEM>>>(xh + t * BATCH * NFEAT, NFEAT,
                                                      h0_in, WP[0], BS + 0 * NGATE,
                                                      Cst + 0 * BH, h0_out);
        lstm_step_mma<HIDDEN><<<grid, 256, DYN_SMEM>>>(h0_out, HIDDEN,
                                                       h1_in, WP[1], BS + 1 * NGATE,
                                                       Cst + 1 * BH, h1_out);
    }

    for (int tt = 0; tt < HORIZONS; tt++) {
        int t = LAGS + tt;
        const __half* h0_in  = Hst + (0 * 2 + (t & 1)) * BH;
        __half*       h0_out = Hst + (0 * 2 + ((t + 1) & 1)) * BH;
        const __half* h1_in  = Hst + (2 + (t & 1)) * BH;
        __half*       h1_out = Hst + (2 + ((t + 1) & 1)) * BH;

        lstm_step_mma<NFEAT><<<grid, 256, DYN_SMEM>>>(decx, NFEAT,
                                                      h0_in, WP[2], BS + 2 * NGATE,
                                                      Cst + 0 * BH, h0_out);
        lstm_step_mma<HIDDEN><<<grid, 256, DYN_SMEM>>>(h0_out, HIDDEN,
                                                       h1_in, WP[3], BS + 3 * NGATE,
                                                       Cst + 1 * BH, h1_out);
        dec_fc<<<BATCH, 256>>>(h1_out, fc1_w, fc1_b, fc4_w, fc4_b, out, tt, decx);
    }
}

// round 8
// speedup vs baseline: 1.3685x; 1.0255x over previous
#include <cuda_runtime.h>
#include <cuda_fp16.h>
#include <cstdint>

// ---------------------------------------------------------------------------
// LSTM Seq2Seq on GB300 — direct-LDG fragment-streaming fp16 mma.sync.
// A (h/x) and B (weights) stored in EXACT mma fragment order in gmem;
// mainloop = LDG.128 -> mma.sync, no smem/cp.async/syncthreads.
// CTA 128m x 32n (8 warps of 64m x 8n), grid (64,4)=256 CTAs, 2 CTAs/SM.
// Fragment conventions (validated by R6/R7 ldmatrix kernel):
//  a-frag (m16,k16) regs q0..q3: q = (m_hi8)*1 + (k_hi8)*2,
//    lane l -> element (r = l>>2, k = 2*(l&3)), u32 = half2(k_even, k_odd)
//  b-frag (n8,k32) 4 slots: koff = q*8, lane l -> (n = l>>2, k = 2*(l&3))
// ---------------------------------------------------------------------------

#define HIDDEN   512
#define BATCH    512
#define NFEAT    32
#define LAGS     96
#define HORIZONS 24
#define NGATE    2048

#define S_L0     17            // k32 stages, K=544
#define S_L1     32            // k32 stages, K=1024

#define BPK0_BYTES (256u * S_L0 * 512u)   // 2228224
#define BPK1_BYTES (256u * S_L1 * 512u)   // 4194304
#define HPK_BYTES  (32u * 32u * 512u)     // 524288 (32 mt x 32 kt x 512B)
#define XPK_T      (32u * 2u * 512u)      // 32768 per timestep

// ---- scratch layout (bytes) ----
#define OFF_B0    0u
#define OFF_B1    (OFF_B0 + BPK0_BYTES)
#define OFF_B2    (OFF_B1 + BPK1_BYTES)
#define OFF_B3    (OFF_B2 + BPK0_BYTES)
#define OFF_BS    (OFF_B3 + BPK1_BYTES)            // float[4*2048]
#define OFF_H0PK  (OFF_BS + 4u * 2048u * 4u)       // 2 x HPK
#define OFF_H1PK  (OFF_H0PK + 2u * HPK_BYTES)      // 2 x HPK
#define OFF_C     (OFF_H1PK + 2u * HPK_BYTES)      // float[2*512*512]
#define OFF_XPK   (OFF_C + 2u * 512u * 512u * 4u)  // 96 x XPK_T
#define OFF_DECX  (OFF_XPK + 96u * XPK_T)          // XPK_T
#define OFF_H1PL  (OFF_DECX + XPK_T)               // half[512*512]
#define SCRATCH_BYTES (OFF_H1PL + 512u * 512u * 2u)

__device__ __align__(1024) unsigned char g_scratch[SCRATCH_BYTES];

// ---------------------------------------------------------------------------
__device__ __forceinline__ void mma_f16(float* d, const uint32_t* a,
                                        uint32_t b0, uint32_t b1) {
    asm volatile(
        "mma.sync.aligned.m16n8k16.row.col.f32.f16.f16.f32 "
        "{%0,%1,%2,%3},{%4,%5,%6,%7},{%8,%9},{%0,%1,%2,%3};"
        : "+f"(d[0]), "+f"(d[1]), "+f"(d[2]), "+f"(d[3])
        : "r"(a[0]), "r"(a[1]), "r"(a[2]), "r"(a[3]), "r"(b0), "r"(b1));
}
__device__ __forceinline__ float fsigmoid(float x) { return 1.f / (1.f + __expf(-x)); }
__device__ __forceinline__ float ftanh(float x)    { return 2.f / (1.f + __expf(-2.f * x)) - 1.f; }
__device__ __forceinline__ uint32_t h2u(float a, float b) {
    __half2 h = __floats2half2_rn(a, b);
    return *(uint32_t*)&h;
}

// ---------------------------------------------------------------------------
// Setup: pack B (4 layers), biases, x (all 96 steps), zero states. Launch #1.
// ---------------------------------------------------------------------------
struct WPtrs { const float* w[16]; };

__global__ void setup_all(const float* __restrict__ src, WPtrs wp)
{
    unsigned char* S = g_scratch;
    const int gs   = gridDim.x * blockDim.x;
    const int tid0 = blockIdx.x * blockDim.x + threadIdx.x;

    const uint32_t boff[4]  = {OFF_B0, OFF_B1, OFF_B2, OFF_B3};
    const int      bstg[4]  = {S_L0, S_L1, S_L0, S_L1};
    const int      indim[4] = {NFEAT, HIDDEN, NFEAT, HIDDEN};

    // ---- B fragment packing ----
    for (int l = 0; l < 4; ++l) {
        const float* Wih = wp.w[l * 4 + 0];
        const float* Whh = wp.w[l * 4 + 1];
        unsigned char* Bp = S + boff[l];
        const int stg = bstg[l], idim = indim[l];
        const int total = 256 * stg * 128;           // u32 slots
        for (int u = tid0; u < total; u += gs) {
            int q    = u & 3;
            int lane = (u >> 2) & 31;
            int s    = (u >> 7) % stg;
            int nt   = (u >> 7) / stg;
            int n = nt * 8 + (lane >> 2);
            int k = s * 32 + q * 8 + 2 * (lane & 3);
            int j = n >> 2, g = n & 3;
            int row = g * HIDDEN + j;
            float v0, v1;
            if (k < idim)          v0 = Wih[row * idim + k];
            else                   v0 = Whh[row * HIDDEN + (k - idim)];
            if (k + 1 < idim)      v1 = Wih[row * idim + k + 1];
            else                   v1 = Whh[row * HIDDEN + (k + 1 - idim)];
            *(uint32_t*)(Bp + ((size_t)(nt * stg + s) * 32 + lane) * 16 + q * 4) = h2u(v0, v1);
        }
        // bias
        const float* bih = wp.w[l * 4 + 2];
        const float* bhh = wp.w[l * 4 + 3];
        float* BS = (float*)(S + OFF_BS);
        for (int n = tid0; n < NGATE; n += gs) {
            int j = n >> 2, g = n & 3;
            BS[l * NGATE + n] = bih[g * HIDDEN + j] + bhh[g * HIDDEN + j];
        }
    }

    // ---- x fragment packing: [t][mt 32][ktl 2][lane 32][q 4] ----
    {
        unsigned char* Xp = S + OFF_XPK;
        const int total = LAGS * 32 * 2 * 128;
        for (int u = tid0; u < total; u += gs) {
            int q    = u & 3;
            int lane = (u >> 2) & 31;
            int ktl  = (u >> 7) & 1;
            int mt   = (u >> 8) & 31;
            int t    = (u >> 13);
            int m = mt * 16 + (q & 1) * 8 + (lane >> 2);
            int k = ktl * 16 + (q >> 1) * 8 + 2 * (lane & 3);
            float v0 = src[m * (LAGS * NFEAT) + t * NFEAT + k];
            float v1 = src[m * (LAGS * NFEAT) + t * NFEAT + k + 1];
            *(uint32_t*)(Xp + (size_t)t * XPK_T +
                         ((size_t)(mt * 2 + ktl) * 32 + lane) * 16 + q * 4) = h2u(v0, v1);
        }
    }

    // ---- zero h-packed (4 buffers), c, h1plain ----
    {
        uint32_t* Z = (uint32_t*)(S + OFF_H0PK);
        int total = (4 * HPK_BYTES + 2 * 512 * 512 * 4) / 4;
        for (int i = tid0; i < total; i += gs) Z[i] = 0;
        uint32_t* P = (uint32_t*)(S + OFF_H1PL);
        for (int i = tid0; i < 512 * 512 * 2 / 4; i += gs) P[i] = 0;
    }
}

// launch #2: initial decx (packed) from src[:, 95, :]
__global__ void init_decx_pk(const float* __restrict__ src)
{
    unsigned char* Dp = g_scratch + OFF_DECX;
    int u = blockIdx.x * blockDim.x + threadIdx.x;
    if (u >= 32 * 2 * 128) return;
    int q    = u & 3;
    int lane = (u >> 2) & 31;
    int ktl  = (u >> 7) & 1;
    int mt   = (u >> 8);
    int m = mt * 16 + (q & 1) * 8 + (lane >> 2);
    int k = ktl * 16 + (q >> 1) * 8 + 2 * (lane & 3);
    float v0 = src[m * (LAGS * NFEAT) + (LAGS - 1) * NFEAT + k];
    float v1 = src[m * (LAGS * NFEAT) + (LAGS - 1) * NFEAT + k + 1];
    *(uint32_t*)(Dp + ((size_t)(mt * 2 + ktl) * 32 + lane) * 16 + q * 4) = h2u(v0, v1);
}

// ---------------------------------------------------------------------------
// Direct-LDG GEMM + fused LSTM cell.
// grid(64, 4): x = n32-tile, y = m128-tile. 256 threads = 8 warps (2m x 4n).
// Warp tile 64m x 8n. S = k32 stages; XKT = k16 tiles in x-region.
// ---------------------------------------------------------------------------
template <int S, int XKT, bool WPLAIN>
__global__ __launch_bounds__(256, 2)
void lstm_step_dl(const unsigned char* __restrict__ xp,  // packed, mt-stride XKT*512
                  const unsigned char* __restrict__ hp,  // packed, mt-stride 32*512
                  const unsigned char* __restrict__ Bp,
                  const float* __restrict__ bs,
                  float* __restrict__ cst,
                  unsigned char* __restrict__ hop,       // packed h out
                  __half* __restrict__ hplain)
{
    const int tid  = threadIdx.x;
    const int w    = tid >> 5, lane = tid & 31;
    const int mgrp = w >> 2, ngrp = w & 3;
    const int mtb  = blockIdx.y * 8 + mgrp * 4;          // warp's first mt (4 tiles)
    const int ntg  = blockIdx.x * 4 + ngrp;              // warp's nt

    const unsigned char* bptr = Bp + ((size_t)ntg * S * 32 + lane) * 16;

    uint4 a[2][4][2];     // [buf][mt][kt-parity]
    uint4 b[2];
    float acc[4][4];
#pragma unroll
    for (int i = 0; i < 4; ++i)
#pragma unroll
        for (int q = 0; q < 4; ++q) acc[i][q] = 0.f;

    auto loadS = [&](int buf, int s) {
        const int kt0 = 2 * s;
        const unsigned char* base;
        int ktl0, mts;
        if (kt0 < XKT) { base = xp; ktl0 = kt0;       mts = XKT * 512; }
        else           { base = hp; ktl0 = kt0 - XKT; mts = 32 * 512;  }
#pragma unroll
        for (int i = 0; i < 4; ++i) {
            const unsigned char* p = base + (size_t)(mtb + i) * mts + (size_t)ktl0 * 512 + lane * 16;
            a[buf][i][0] = *(const uint4*)p;
            a[buf][i][1] = *(const uint4*)(p + 512);
        }
        b[buf] = *(const uint4*)(bptr + (size_t)s * 512);
    };

    loadS(0, 0);
#pragma unroll 4
    for (int s = 0; s < S; ++s) {
        const int cb = s & 1;
        if (s + 1 < S) loadS(cb ^ 1, s + 1);
#pragma unroll
        for (int i = 0; i < 4; ++i) {
            mma_f16(acc[i], (const uint32_t*)&a[cb][i][0], b[cb].x, b[cb].y);
            mma_f16(acc[i], (const uint32_t*)&a[cb][i][1], b[cb].z, b[cb].w);
        }
    }

    // ---- epilogue: accs -> smem z [128][36] -> fused cell ----
    __shared__ float zs[128 * 36];
#pragma unroll
    for (int i = 0; i < 4; ++i) {
        int r = mgrp * 64 + i * 16 + (lane >> 2);
        int c = ngrp * 8 + 2 * (lane & 3);
        *(float2*)&zs[r * 36 + c]       = make_float2(acc[i][0], acc[i][1]);
        *(float2*)&zs[(r + 8) * 36 + c] = make_float2(acc[i][2], acc[i][3]);
    }
    __syncthreads();

    {
        const int bl  = tid >> 1;                  // 0..127
        const int grp = tid & 1;                   // j4-group
        const int bg  = blockIdx.y * 128 + bl;     // global batch row
        const int j0  = blockIdx.x * 8 + grp * 4;  // global j (4 consecutive)
        const int n0  = blockIdx.x * 32 + grp * 16;

        const float* zrow = &zs[bl * 36 + grp * 16];
        float4 cold = *(const float4*)&cst[bg * HIDDEN + j0];
        float cOld[4] = {cold.x, cold.y, cold.z, cold.w};
        float hv[4], cN[4];
#pragma unroll
        for (int q = 0; q < 4; ++q) {
            float4 z4 = *(const float4*)&zrow[q * 4];
            float4 b4 = *(const float4*)&bs[n0 + q * 4];
            float zi = z4.x + b4.x;
            float zf = z4.y + b4.y;
            float zg = z4.z + b4.z;
            float zo = z4.w + b4.w;
            float cn = fsigmoid(zf) * cOld[q] + fsigmoid(zi) * ftanh(zg);
            cN[q] = cn;
            hv[q] = fsigmoid(zo) * ftanh(cn);
        }
        *(float4*)&cst[bg * HIDDEN + j0] = make_float4(cN[0], cN[1], cN[2], cN[3]);

        // packed h store (fragment layout)
        {
            int kt = j0 >> 4, kk = j0 & 15;
            int mt = bg >> 4, r = bg & 15;
            int q  = ((r >> 3) & 1) + ((kk >> 3) & 1) * 2;
            int l0 = ((r & 7) << 2) + ((kk & 7) >> 1);
            unsigned char* base = hop + ((size_t)(mt * 32 + kt) * 32 + l0) * 16 + q * 4;
            *(uint32_t*)base        = h2u(hv[0], hv[1]);
            *(uint32_t*)(base + 16) = h2u(hv[2], hv[3]);
        }
        if (WPLAIN) {
            __half2 p0 = __floats2half2_rn(hv[0], hv[1]);
            __half2 p1 = __floats2half2_rn(hv[2], hv[3]);
            *(uint2*)&hplain[bg * HIDDEN + j0] =
                make_uint2(*(uint32_t*)&p0, *(uint32_t*)&p1);
        }
    }
}

// ---------------------------------------------------------------------------
// Decoder heads: out[b][t] = h1·fc1 + b1 ; decx_packed = h1·fc4^T + b4
// ---------------------------------------------------------------------------
__global__ __launch_bounds__(256)
void dec_fc(const __half* __restrict__ h1,
            const float* __restrict__ fc1_w, const float* __restrict__ fc1_b,
            const float* __restrict__ fc4_w, const float* __restrict__ fc4_b,
            float* __restrict__ out, int t)
{
    unsigned char* Dp = g_scratch + OFF_DECX;
    __shared__ float sh[HIDDEN];
    const int b = blockIdx.x;
    for (int i = threadIdx.x; i < HIDDEN; i += blockDim.x)
        sh[i] = __half2float(h1[b * HIDDEN + i]);
    __syncthreads();

    const int warp = threadIdx.x >> 5;
    const int lane = threadIdx.x & 31;
    for (int o = warp; o < 1 + NFEAT; o += 8) {
        const float* w = (o == 0) ? fc1_w : (fc4_w + (o - 1) * HIDDEN);
        float s = 0.f;
#pragma unroll 4
        for (int k = lane; k < HIDDEN; k += 32) s += sh[k] * w[k];
#pragma unroll
        for (int off = 16; off; off >>= 1) s += __shfl_down_sync(0xffffffffu, s, off);
        if (lane == 0) {
            if (o == 0) {
                out[b * HORIZONS + t] = s + fc1_b[0];
            } else {
                int f = o - 1;
                float v = s + fc4_b[f];
                int ktl = f >> 4, kk = f & 15;
                int mt = b >> 4, r = b & 15;
                int q  = ((r >> 3) & 1) + ((kk >> 3) & 1) * 2;
                int l0 = ((r & 7) << 2) + ((kk & 7) >> 1);
                unsigned char* addr = Dp + ((size_t)(mt * 2 + ktl) * 32 + l0) * 16
                                      + q * 4 + (kk & 1) * 2;
                *(__half*)addr = __float2half_rn(v);
            }
        }
    }
}

// ---------------------------------------------------------------------------
extern "C" void kernel_launch(void* const* d_in, const int* in_sizes, int n_in,
                              void* d_out, int out_size)
{
    const int wb = (in_sizes[2] == 1) ? 3 : 2;

    const float* src = (const float*)d_in[0];
    WPtrs wp;
    for (int i = 0; i < 16; i++) wp.w[i] = (const float*)d_in[wb + i];
    const float* fc1_w = (const float*)d_in[wb + 16];
    const float* fc1_b = (const float*)d_in[wb + 17];
    const float* fc4_w = (const float*)d_in[wb + 18];
    const float* fc4_b = (const float*)d_in[wb + 19];
    float* out = (float*)d_out;

    unsigned char* S = nullptr;
    cudaGetSymbolAddress((void**)&S, g_scratch);

    unsigned char* B0 = S + OFF_B0;
    unsigned char* B1 = S + OFF_B1;
    unsigned char* B2 = S + OFF_B2;
    unsigned char* B3 = S + OFF_B3;
    float* BS = (float*)(S + OFF_BS);
    unsigned char* H0PK[2] = {S + OFF_H0PK, S + OFF_H0PK + HPK_BYTES};
    unsigned char* H1PK[2] = {S + OFF_H1PK, S + OFF_H1PK + HPK_BYTES};
    float* C0 = (float*)(S + OFF_C);
    float* C1 = C0 + 512 * 512;
    unsigned char* XPK  = S + OFF_XPK;
    unsigned char* DECX = S + OFF_DECX;
    __half* H1PL = (__half*)(S + OFF_H1PL);

    // launch #1, #2  ->  ncu -s 5 lands on launch #6 = l1(t=1)
    setup_all<<<1024, 256>>>(src, wp);
    init_decx_pk<<<(32 * 2 * 128 + 255) / 256, 256>>>(src);

    dim3 grid(64, 4);   // 256 CTAs

    for (int t = 0; t < LAGS; t++) {
        lstm_step_dl<S_L0, 2, false><<<grid, 256>>>(
            XPK + (size_t)t * XPK_T, H0PK[t & 1], B0, BS + 0 * NGATE,
            C0, H0PK[(t + 1) & 1], nullptr);
        lstm_step_dl<S_L1, 32, false><<<grid, 256>>>(
            H0PK[(t + 1) & 1], H1PK[t & 1], B1, BS + 1 * NGATE,
            C1, H1PK[(t + 1) & 1], nullptr);
    }

    for (int tt = 0; tt < HORIZONS; tt++) {
        int t = LAGS + tt;
        lstm_step_dl<S_L0, 2, false><<<grid, 256>>>(
            DECX, H0PK[t & 1], B2, BS + 2 * NGATE,
            C0, H0PK[(t + 1) & 1], nullptr);
        lstm_step_dl<S_L1, 32, true><<<grid, 256>>>(
            H0PK[(t + 1) & 1], H1PK[t & 1], B3, BS + 3 * NGATE,
            C1, H1PK[(t + 1) & 1], H1PL);
        dec_fc<<<BATCH, 256>>>(H1PL, fc1_w, fc1_b, fc4_w, fc4_b, out, tt);
    }
}

// round 9
// speedup vs baseline: 1.4367x; 1.0498x over previous
#include <cuda_runtime.h>
#include <cuda_fp16.h>
#include <cstdint>

// ---------------------------------------------------------------------------
// LSTM Seq2Seq on GB300 — direct-LDG fragment-streaming fp16 mma.sync.
// R9: square warp tiles 32m x 32n (8 LDG -> 16 MMA), CTA 64x64 with 4 warps,
// grid 256, 4 CTAs/SM. Halves L1 wavefronts per MMA vs R8 and doubles
// warps/SM. Fragment layouts identical to R8 (validated).
// ---------------------------------------------------------------------------

#define HIDDEN   512
#define BATCH    512
#define NFEAT    32
#define LAGS     96
#define HORIZONS 24
#define NGATE    2048

#define S_L0     17            // k32 stages, K=544
#define S_L1     32            // k32 stages, K=1024

#define BPK0_BYTES (256u * S_L0 * 512u)
#define BPK1_BYTES (256u * S_L1 * 512u)
#define HPK_BYTES  (32u * 32u * 512u)     // 32 mt x 32 kt x 512B
#define XPK_T      (32u * 2u * 512u)      // per timestep

// ---- scratch layout (bytes) ----
#define OFF_B0    0u
#define OFF_B1    (OFF_B0 + BPK0_BYTES)
#define OFF_B2    (OFF_B1 + BPK1_BYTES)
#define OFF_B3    (OFF_B2 + BPK0_BYTES)
#define OFF_BS    (OFF_B3 + BPK1_BYTES)            // float[4*2048]
#define OFF_H0PK  (OFF_BS + 4u * 2048u * 4u)       // 2 x HPK
#define OFF_H1PK  (OFF_H0PK + 2u * HPK_BYTES)      // 2 x HPK
#define OFF_C     (OFF_H1PK + 2u * HPK_BYTES)      // float[2*512*512]
#define OFF_XPK   (OFF_C + 2u * 512u * 512u * 4u)  // 96 x XPK_T
#define OFF_DECX  (OFF_XPK + 96u * XPK_T)          // XPK_T
#define OFF_H1PL  (OFF_DECX + XPK_T)               // half[512*512]
#define SCRATCH_BYTES (OFF_H1PL + 512u * 512u * 2u)

__device__ __align__(1024) unsigned char g_scratch[SCRATCH_BYTES];

// ---------------------------------------------------------------------------
__device__ __forceinline__ void mma_f16(float* d, const uint32_t* a,
                                        uint32_t b0, uint32_t b1) {
    asm volatile(
        "mma.sync.aligned.m16n8k16.row.col.f32.f16.f16.f32 "
        "{%0,%1,%2,%3},{%4,%5,%6,%7},{%8,%9},{%0,%1,%2,%3};"
        : "+f"(d[0]), "+f"(d[1]), "+f"(d[2]), "+f"(d[3])
        : "r"(a[0]), "r"(a[1]), "r"(a[2]), "r"(a[3]), "r"(b0), "r"(b1));
}
__device__ __forceinline__ float fsigmoid(float x) { return 1.f / (1.f + __expf(-x)); }
__device__ __forceinline__ float ftanh(float x)    { return 2.f / (1.f + __expf(-2.f * x)) - 1.f; }
__device__ __forceinline__ uint32_t h2u(float a, float b) {
    __half2 h = __floats2half2_rn(a, b);
    return *(uint32_t*)&h;
}

// ---------------------------------------------------------------------------
// Setup (launch #1): pack B (4 layers), biases, x (96 steps), zero states.
// ---------------------------------------------------------------------------
struct WPtrs { const float* w[16]; };

__global__ void setup_all(const float* __restrict__ src, WPtrs wp)
{
    unsigned char* S = g_scratch;
    const int gs   = gridDim.x * blockDim.x;
    const int tid0 = blockIdx.x * blockDim.x + threadIdx.x;

    const uint32_t boff[4]  = {OFF_B0, OFF_B1, OFF_B2, OFF_B3};
    const int      bstg[4]  = {S_L0, S_L1, S_L0, S_L1};
    const int      indim[4] = {NFEAT, HIDDEN, NFEAT, HIDDEN};

    for (int l = 0; l < 4; ++l) {
        const float* Wih = wp.w[l * 4 + 0];
        const float* Whh = wp.w[l * 4 + 1];
        unsigned char* Bp = S + boff[l];
        const int stg = bstg[l], idim = indim[l];
        const int total = 256 * stg * 128;
        for (int u = tid0; u < total; u += gs) {
            int q    = u & 3;
            int lane = (u >> 2) & 31;
            int s    = (u >> 7) % stg;
            int nt   = (u >> 7) / stg;
            int n = nt * 8 + (lane >> 2);
            int k = s * 32 + q * 8 + 2 * (lane & 3);
            int j = n >> 2, g = n & 3;
            int row = g * HIDDEN + j;
            float v0, v1;
            if (k < idim)          v0 = Wih[row * idim + k];
            else                   v0 = Whh[row * HIDDEN + (k - idim)];
            if (k + 1 < idim)      v1 = Wih[row * idim + k + 1];
            else                   v1 = Whh[row * HIDDEN + (k + 1 - idim)];
            *(uint32_t*)(Bp + ((size_t)(nt * stg + s) * 32 + lane) * 16 + q * 4) = h2u(v0, v1);
        }
        const float* bih = wp.w[l * 4 + 2];
        const float* bhh = wp.w[l * 4 + 3];
        float* BS = (float*)(S + OFF_BS);
        for (int n = tid0; n < NGATE; n += gs) {
            int j = n >> 2, g = n & 3;
            BS[l * NGATE + n] = bih[g * HIDDEN + j] + bhh[g * HIDDEN + j];
        }
    }

    {   // x fragment packing: [t][mt 32][ktl 2][lane 32][q 4]
        unsigned char* Xp = S + OFF_XPK;
        const int total = LAGS * 32 * 2 * 128;
        for (int u = tid0; u < total; u += gs) {
            int q    = u & 3;
            int lane = (u >> 2) & 31;
            int ktl  = (u >> 7) & 1;
            int mt   = (u >> 8) & 31;
            int t    = (u >> 13);
            int m = mt * 16 + (q & 1) * 8 + (lane >> 2);
            int k = ktl * 16 + (q >> 1) * 8 + 2 * (lane & 3);
            float v0 = src[m * (LAGS * NFEAT) + t * NFEAT + k];
            float v1 = src[m * (LAGS * NFEAT) + t * NFEAT + k + 1];
            *(uint32_t*)(Xp + (size_t)t * XPK_T +
                         ((size_t)(mt * 2 + ktl) * 32 + lane) * 16 + q * 4) = h2u(v0, v1);
        }
    }

    {   // zero h-packed (4 buffers), c, h1plain
        uint32_t* Z = (uint32_t*)(S + OFF_H0PK);
        int total = (4 * HPK_BYTES + 2 * 512 * 512 * 4) / 4;
        for (int i = tid0; i < total; i += gs) Z[i] = 0;
        uint32_t* P = (uint32_t*)(S + OFF_H1PL);
        for (int i = tid0; i < 512 * 512 * 2 / 4; i += gs) P[i] = 0;
    }
}

// launch #2: initial decx (packed) from src[:, 95, :]
__global__ void init_decx_pk(const float* __restrict__ src)
{
    unsigned char* Dp = g_scratch + OFF_DECX;
    int u = blockIdx.x * blockDim.x + threadIdx.x;
    if (u >= 32 * 2 * 128) return;
    int q    = u & 3;
    int lane = (u >> 2) & 31;
    int ktl  = (u >> 7) & 1;
    int mt   = (u >> 8);
    int m = mt * 16 + (q & 1) * 8 + (lane >> 2);
    int k = ktl * 16 + (q >> 1) * 8 + 2 * (lane & 3);
    float v0 = src[m * (LAGS * NFEAT) + (LAGS - 1) * NFEAT + k];
    float v1 = src[m * (LAGS * NFEAT) + (LAGS - 1) * NFEAT + k + 1];
    *(uint32_t*)(Dp + ((size_t)(mt * 2 + ktl) * 32 + lane) * 16 + q * 4) = h2u(v0, v1);
}

// ---------------------------------------------------------------------------
// Direct-LDG GEMM + fused LSTM cell.
// grid(32, 8): x = n64-tile (16 j), y = m64-tile. 128 threads = 4 warps
// (2m x 2n), warp tile 32m x 32n. Per warp per k32 stage: 4 A-LDG.128 +
// 4 B-LDG.128 -> 16 MMA.
// ---------------------------------------------------------------------------
template <int S, int XKT, bool WPLAIN>
__global__ __launch_bounds__(128, 4)
void lstm_step_dl(const unsigned char* __restrict__ xp,  // packed, mt-stride XKT*512
                  const unsigned char* __restrict__ hp,  // packed, mt-stride 32*512
                  const unsigned char* __restrict__ Bp,
                  const float* __restrict__ bs,
                  float* __restrict__ cst,
                  unsigned char* __restrict__ hop,       // packed h out
                  __half* __restrict__ hplain)
{
    const int tid  = threadIdx.x;
    const int w    = tid >> 5, lane = tid & 31;
    const int mgrp = w >> 1, ngrp = w & 1;
    const int mtb  = blockIdx.y * 4 + mgrp * 2;          // warp's first mt (2 tiles)
    const int ntb  = blockIdx.x * 8 + ngrp * 4;          // warp's first nt (4 tiles)

    const unsigned char* bptr = Bp + ((size_t)ntb * S * 32 + lane) * 16;

    uint4 a[2][2][2];     // [buf][mt][kt-parity]
    uint4 b[2][4];        // [buf][nt]
    float acc[2][4][4];
#pragma unroll
    for (int i = 0; i < 2; ++i)
#pragma unroll
        for (int nf = 0; nf < 4; ++nf)
#pragma unroll
            for (int q = 0; q < 4; ++q) acc[i][nf][q] = 0.f;

    auto loadS = [&](int buf, int s) {
        const int kt0 = 2 * s;
        const unsigned char* base;
        int ktl0, mts;
        if (kt0 < XKT) { base = xp; ktl0 = kt0;       mts = XKT * 512; }
        else           { base = hp; ktl0 = kt0 - XKT; mts = 32 * 512;  }
#pragma unroll
        for (int i = 0; i < 2; ++i) {
            const unsigned char* p = base + (size_t)(mtb + i) * mts + (size_t)ktl0 * 512 + lane * 16;
            a[buf][i][0] = *(const uint4*)p;
            a[buf][i][1] = *(const uint4*)(p + 512);
        }
#pragma unroll
        for (int j = 0; j < 4; ++j)
            b[buf][j] = *(const uint4*)(bptr + ((size_t)j * S + s) * 512);
    };

    loadS(0, 0);
#pragma unroll 4
    for (int s = 0; s < S; ++s) {
        const int cb = s & 1;
        if (s + 1 < S) loadS(cb ^ 1, s + 1);
#pragma unroll
        for (int i = 0; i < 2; ++i)
#pragma unroll
            for (int nf = 0; nf < 4; ++nf) {
                mma_f16(acc[i][nf], (const uint32_t*)&a[cb][i][0], b[cb][nf].x, b[cb][nf].y);
                mma_f16(acc[i][nf], (const uint32_t*)&a[cb][i][1], b[cb][nf].z, b[cb][nf].w);
            }
    }

    // ---- epilogue: accs -> smem z [64][68] -> fused cell ----
    __shared__ float zs[64 * 68];
#pragma unroll
    for (int i = 0; i < 2; ++i)
#pragma unroll
        for (int nf = 0; nf < 4; ++nf) {
            int r = mgrp * 32 + i * 16 + (lane >> 2);
            int c = ngrp * 32 + nf * 8 + 2 * (lane & 3);
            *(float2*)&zs[r * 68 + c]       = make_float2(acc[i][nf][0], acc[i][nf][1]);
            *(float2*)&zs[(r + 8) * 68 + c] = make_float2(acc[i][nf][2], acc[i][nf][3]);
        }
    __syncthreads();

    {
        const int row = tid >> 1;                  // 0..63 local batch row
        const int grp = tid & 1;                   // 8-j half
        const int bg  = blockIdx.y * 64 + row;     // global batch row
        const int j0  = blockIdx.x * 16 + grp * 8; // global j (8 consecutive)
        const int n0  = blockIdx.x * 64 + grp * 32;

        const float* zrow = &zs[row * 68 + grp * 32];
        float4 cA = *(const float4*)&cst[bg * HIDDEN + j0];
        float4 cB = *(const float4*)&cst[bg * HIDDEN + j0 + 4];
        float cOld[8] = {cA.x, cA.y, cA.z, cA.w, cB.x, cB.y, cB.z, cB.w};
        float hv[8], cN[8];
#pragma unroll
        for (int q = 0; q < 8; ++q) {
            float4 z4 = *(const float4*)&zrow[q * 4];
            float4 b4 = *(const float4*)&bs[n0 + q * 4];
            float zi = z4.x + b4.x;
            float zf = z4.y + b4.y;
            float zg = z4.z + b4.z;
            float zo = z4.w + b4.w;
            float cn = fsigmoid(zf) * cOld[q] + fsigmoid(zi) * ftanh(zg);
            cN[q] = cn;
            hv[q] = fsigmoid(zo) * ftanh(cn);
        }
        *(float4*)&cst[bg * HIDDEN + j0]     = make_float4(cN[0], cN[1], cN[2], cN[3]);
        *(float4*)&cst[bg * HIDDEN + j0 + 4] = make_float4(cN[4], cN[5], cN[6], cN[7]);

        // packed h store (fragment layout); j0 is 8-aligned -> quadrant bits const
        {
            int kt = j0 >> 4, kkb = j0 & 15;
            int mt = bg >> 4, r = bg & 15;
            int q  = ((r >> 3) & 1) + ((kkb >> 3) & 1) * 2;
            unsigned char* base = hop + ((size_t)(mt * 32 + kt) * 32 + ((r & 7) << 2)) * 16 + q * 4;
#pragma unroll
            for (int qq = 0; qq < 4; ++qq)
                *(uint32_t*)(base + qq * 16) = h2u(hv[2 * qq], hv[2 * qq + 1]);
        }
        if (WPLAIN) {
            __half2 p0 = __floats2half2_rn(hv[0], hv[1]);
            __half2 p1 = __floats2half2_rn(hv[2], hv[3]);
            __half2 p2 = __floats2half2_rn(hv[4], hv[5]);
            __half2 p3 = __floats2half2_rn(hv[6], hv[7]);
            *(uint4*)&hplain[bg * HIDDEN + j0] =
                make_uint4(*(uint32_t*)&p0, *(uint32_t*)&p1,
                           *(uint32_t*)&p2, *(uint32_t*)&p3);
        }
    }
}

// ---------------------------------------------------------------------------
// Decoder heads: out[b][t] = h1·fc1 + b1 ; decx_packed = h1·fc4^T + b4
// ---------------------------------------------------------------------------
__global__ __launch_bounds__(256)
void dec_fc(const __half* __restrict__ h1,
            const float* __restrict__ fc1_w, const float* __restrict__ fc1_b,
            const float* __restrict__ fc4_w, const float* __restrict__ fc4_b,
            float* __restrict__ out, int t)
{
    unsigned char* Dp = g_scratch + OFF_DECX;
    __shared__ float sh[HIDDEN];
    const int b = blockIdx.x;
    for (int i = threadIdx.x; i < HIDDEN; i += blockDim.x)
        sh[i] = __half2float(h1[b * HIDDEN + i]);
    __syncthreads();

    const int warp = threadIdx.x >> 5;
    const int lane = threadIdx.x & 31;
    for (int o = warp; o < 1 + NFEAT; o += 8) {
        const float* w = (o == 0) ? fc1_w : (fc4_w + (o - 1) * HIDDEN);
        float s = 0.f;
#pragma unroll 4
        for (int k = lane; k < HIDDEN; k += 32) s += sh[k] * w[k];
#pragma unroll
        for (int off = 16; off; off >>= 1) s += __shfl_down_sync(0xffffffffu, s, off);
        if (lane == 0) {
            if (o == 0) {
                out[b * HORIZONS + t] = s + fc1_b[0];
            } else {
                int f = o - 1;
                float v = s + fc4_b[f];
                int ktl = f >> 4, kk = f & 15;
                int mt = b >> 4, r = b & 15;
                int q  = ((r >> 3) & 1) + ((kk >> 3) & 1) * 2;
                int l0 = ((r & 7) << 2) + ((kk & 7) >> 1);
                unsigned char* addr = Dp + ((size_t)(mt * 2 + ktl) * 32 + l0) * 16
                                      + q * 4 + (kk & 1) * 2;
                *(__half*)addr = __float2half_rn(v);
            }
        }
    }
}

// ---------------------------------------------------------------------------
extern "C" void kernel_launch(void* const* d_in, const int* in_sizes, int n_in,
                              void* d_out, int out_size)
{
    const int wb = (in_sizes[2] == 1) ? 3 : 2;

    const float* src = (const float*)d_in[0];
    WPtrs wp;
    for (int i = 0; i < 16; i++) wp.w[i] = (const float*)d_in[wb + i];
    const float* fc1_w = (const float*)d_in[wb + 16];
    const float* fc1_b = (const float*)d_in[wb + 17];
    const float* fc4_w = (const float*)d_in[wb + 18];
    const float* fc4_b = (const float*)d_in[wb + 19];
    float* out = (float*)d_out;

    unsigned char* S = nullptr;
    cudaGetSymbolAddress((void**)&S, g_scratch);

    unsigned char* B0 = S + OFF_B0;
    unsigned char* B1 = S + OFF_B1;
    unsigned char* B2 = S + OFF_B2;
    unsigned char* B3 = S + OFF_B3;
    float* BS = (float*)(S + OFF_BS);
    unsigned char* H0PK[2] = {S + OFF_H0PK, S + OFF_H0PK + HPK_BYTES};
    unsigned char* H1PK[2] = {S + OFF_H1PK, S + OFF_H1PK + HPK_BYTES};
    float* C0 = (float*)(S + OFF_C);
    float* C1 = C0 + 512 * 512;
    unsigned char* XPK  = S + OFF_XPK;
    unsigned char* DECX = S + OFF_DECX;
    __half* H1PL = (__half*)(S + OFF_H1PL);

    // launch #1, #2  ->  ncu -s 5 lands on launch #6 = l1(t=1)
    setup_all<<<1024, 256>>>(src, wp);
    init_decx_pk<<<(32 * 2 * 128 + 255) / 256, 256>>>(src);

    dim3 grid(32, 8);   // 256 CTAs, 128 threads each

    for (int t = 0; t < LAGS; t++) {
        lstm_step_dl<S_L0, 2, false><<<grid, 128>>>(
            XPK + (size_t)t * XPK_T, H0PK[t & 1], B0, BS + 0 * NGATE,
            C0, H0PK[(t + 1) & 1], nullptr);
        lstm_step_dl<S_L1, 32, false><<<grid, 128>>>(
            H0PK[(t + 1) & 1], H1PK[t & 1], B1, BS + 1 * NGATE,
            C1, H1PK[(t + 1) & 1], nullptr);
    }

    for (int tt = 0; tt < HORIZONS; tt++) {
        int t = LAGS + tt;
        lstm_step_dl<S_L0, 2, false><<<grid, 128>>>(
            DECX, H0PK[t & 1], B2, BS + 2 * NGATE,
            C0, H0PK[(t + 1) & 1], nullptr);
        lstm_step_dl<S_L1, 32, true><<<grid, 128>>>(
            H0PK[(t + 1) & 1], H1PK[t & 1], B3, BS + 3 * NGATE,
            C1, H1PK[(t + 1) & 1], H1PL);
        dec_fc<<<BATCH, 256>>>(H1PL, fc1_w, fc1_b, fc4_w, fc4_b, out, tt);
    }
}

// round 10
// speedup vs baseline: 1.6591x; 1.1548x over previous
#include <cuda_runtime.h>
#include <cuda_fp16.h>
#include <cstdint>

// ---------------------------------------------------------------------------
// LSTM Seq2Seq on GB300 — direct-LDG fragment-streaming fp16 mma.sync.
// R10: CTA 64m x 64n, 8 warps (2m x 4n), warp tile 32m x 16n.
// 3 L1-wavefronts per MMA (vs R8 4.5) at R8's occupancy (2048 warps).
// Fragment layouts identical to R8/R9 (validated).
// ---------------------------------------------------------------------------

#define HIDDEN   512
#define BATCH    512
#define NFEAT    32
#define LAGS     96
#define HORIZONS 24
#define NGATE    2048

#define S_L0     17            // k32 stages, K=544
#define S_L1     32            // k32 stages, K=1024

#define BPK0_BYTES (256u * S_L0 * 512u)
#define BPK1_BYTES (256u * S_L1 * 512u)
#define HPK_BYTES  (32u * 32u * 512u)     // 32 mt x 32 kt x 512B
#define XPK_T      (32u * 2u * 512u)      // per timestep

// ---- scratch layout (bytes) ----
#define OFF_B0    0u
#define OFF_B1    (OFF_B0 + BPK0_BYTES)
#define OFF_B2    (OFF_B1 + BPK1_BYTES)
#define OFF_B3    (OFF_B2 + BPK0_BYTES)
#define OFF_BS    (OFF_B3 + BPK1_BYTES)            // float[4*2048]
#define OFF_H0PK  (OFF_BS + 4u * 2048u * 4u)       // 2 x HPK
#define OFF_H1PK  (OFF_H0PK + 2u * HPK_BYTES)      // 2 x HPK
#define OFF_C     (OFF_H1PK + 2u * HPK_BYTES)      // float[2*512*512]
#define OFF_XPK   (OFF_C + 2u * 512u * 512u * 4u)  // 96 x XPK_T
#define OFF_DECX  (OFF_XPK + 96u * XPK_T)          // XPK_T
#define OFF_H1PL  (OFF_DECX + XPK_T)               // half[512*512]
#define SCRATCH_BYTES (OFF_H1PL + 512u * 512u * 2u)

__device__ __align__(1024) unsigned char g_scratch[SCRATCH_BYTES];

// ---------------------------------------------------------------------------
__device__ __forceinline__ void mma_f16(float* d, const uint32_t* a,
                                        uint32_t b0, uint32_t b1) {
    asm volatile(
        "mma.sync.aligned.m16n8k16.row.col.f32.f16.f16.f32 "
        "{%0,%1,%2,%3},{%4,%5,%6,%7},{%8,%9},{%0,%1,%2,%3};"
        : "+f"(d[0]), "+f"(d[1]), "+f"(d[2]), "+f"(d[3])
        : "r"(a[0]), "r"(a[1]), "r"(a[2]), "r"(a[3]), "r"(b0), "r"(b1));
}
__device__ __forceinline__ float fsigmoid(float x) { return 1.f / (1.f + __expf(-x)); }
__device__ __forceinline__ float ftanh(float x)    { return 2.f / (1.f + __expf(-2.f * x)) - 1.f; }
__device__ __forceinline__ uint32_t h2u(float a, float b) {
    __half2 h = __floats2half2_rn(a, b);
    return *(uint32_t*)&h;
}

// ---------------------------------------------------------------------------
// Setup (launch #1): pack B (4 layers), biases, x (96 steps), zero states.
// ---------------------------------------------------------------------------
struct WPtrs { const float* w[16]; };

__global__ void setup_all(const float* __restrict__ src, WPtrs wp)
{
    unsigned char* S = g_scratch;
    const int gs   = gridDim.x * blockDim.x;
    const int tid0 = blockIdx.x * blockDim.x + threadIdx.x;

    const uint32_t boff[4]  = {OFF_B0, OFF_B1, OFF_B2, OFF_B3};
    const int      bstg[4]  = {S_L0, S_L1, S_L0, S_L1};
    const int      indim[4] = {NFEAT, HIDDEN, NFEAT, HIDDEN};

    for (int l = 0; l < 4; ++l) {
        const float* Wih = wp.w[l * 4 + 0];
        const float* Whh = wp.w[l * 4 + 1];
        unsigned char* Bp = S + boff[l];
        const int stg = bstg[l], idim = indim[l];
        const int total = 256 * stg * 128;
        for (int u = tid0; u < total; u += gs) {
            int q    = u & 3;
            int lane = (u >> 2) & 31;
            int s    = (u >> 7) % stg;
            int nt   = (u >> 7) / stg;
            int n = nt * 8 + (lane >> 2);
            int k = s * 32 + q * 8 + 2 * (lane & 3);
            int j = n >> 2, g = n & 3;
            int row = g * HIDDEN + j;
            float v0, v1;
            if (k < idim)          v0 = Wih[row * idim + k];
            else                   v0 = Whh[row * HIDDEN + (k - idim)];
            if (k + 1 < idim)      v1 = Wih[row * idim + k + 1];
            else                   v1 = Whh[row * HIDDEN + (k + 1 - idim)];
            *(uint32_t*)(Bp + ((size_t)(nt * stg + s) * 32 + lane) * 16 + q * 4) = h2u(v0, v1);
        }
        const float* bih = wp.w[l * 4 + 2];
        const float* bhh = wp.w[l * 4 + 3];
        float* BS = (float*)(S + OFF_BS);
        for (int n = tid0; n < NGATE; n += gs) {
            int j = n >> 2, g = n & 3;
            BS[l * NGATE + n] = bih[g * HIDDEN + j] + bhh[g * HIDDEN + j];
        }
    }

    {   // x fragment packing: [t][mt 32][ktl 2][lane 32][q 4]
        unsigned char* Xp = S + OFF_XPK;
        const int total = LAGS * 32 * 2 * 128;
        for (int u = tid0; u < total; u += gs) {
            int q    = u & 3;
            int lane = (u >> 2) & 31;
            int ktl  = (u >> 7) & 1;
            int mt   = (u >> 8) & 31;
            int t    = (u >> 13);
            int m = mt * 16 + (q & 1) * 8 + (lane >> 2);
            int k = ktl * 16 + (q >> 1) * 8 + 2 * (lane & 3);
            float v0 = src[m * (LAGS * NFEAT) + t * NFEAT + k];
            float v1 = src[m * (LAGS * NFEAT) + t * NFEAT + k + 1];
            *(uint32_t*)(Xp + (size_t)t * XPK_T +
                         ((size_t)(mt * 2 + ktl) * 32 + lane) * 16 + q * 4) = h2u(v0, v1);
        }
    }

    {   // zero h-packed (4 buffers), c, h1plain
        uint32_t* Z = (uint32_t*)(S + OFF_H0PK);
        int total = (4 * HPK_BYTES + 2 * 512 * 512 * 4) / 4;
        for (int i = tid0; i < total; i += gs) Z[i] = 0;
        uint32_t* P = (uint32_t*)(S + OFF_H1PL);
        for (int i = tid0; i < 512 * 512 * 2 / 4; i += gs) P[i] = 0;
    }
}

// launch #2: initial decx (packed) from src[:, 95, :]
__global__ void init_decx_pk(const float* __restrict__ src)
{
    unsigned char* Dp = g_scratch + OFF_DECX;
    int u = blockIdx.x * blockDim.x + threadIdx.x;
    if (u >= 32 * 2 * 128) return;
    int q    = u & 3;
    int lane = (u >> 2) & 31;
    int ktl  = (u >> 7) & 1;
    int mt   = (u >> 8);
    int m = mt * 16 + (q & 1) * 8 + (lane >> 2);
    int k = ktl * 16 + (q >> 1) * 8 + 2 * (lane & 3);
    float v0 = src[m * (LAGS * NFEAT) + (LAGS - 1) * NFEAT + k];
    float v1 = src[m * (LAGS * NFEAT) + (LAGS - 1) * NFEAT + k + 1];
    *(uint32_t*)(Dp + ((size_t)(mt * 2 + ktl) * 32 + lane) * 16 + q * 4) = h2u(v0, v1);
}

// ---------------------------------------------------------------------------
// Direct-LDG GEMM + fused LSTM cell.
// grid(32, 8): x = n64-tile (16 j), y = m64-tile. 256 threads = 8 warps
// (2 mgrp x 4 ngrp), warp tile 32m x 16n. Per warp per k32 stage:
// 4 A-LDG.128 + 2 B-LDG.128 -> 8 MMA (3 wavefronts/MMA).
// ---------------------------------------------------------------------------
template <int S, int XKT, bool WPLAIN>
__global__ __launch_bounds__(256, 2)
void lstm_step_dl(const unsigned char* __restrict__ xp,  // packed, mt-stride XKT*512
                  const unsigned char* __restrict__ hp,  // packed, mt-stride 32*512
                  const unsigned char* __restrict__ Bp,
                  const float* __restrict__ bs,
                  float* __restrict__ cst,
                  unsigned char* __restrict__ hop,       // packed h out
                  __half* __restrict__ hplain)
{
    const int tid  = threadIdx.x;
    const int w    = tid >> 5, lane = tid & 31;
    const int mgrp = w >> 2, ngrp = w & 3;
    const int mtb  = blockIdx.y * 4 + mgrp * 2;          // warp's first mt (2 tiles)
    const int ntb  = blockIdx.x * 8 + ngrp * 2;          // warp's first nt (2 tiles)

    const unsigned char* bptr = Bp + ((size_t)ntb * S * 32 + lane) * 16;

    uint4 a[2][2][2];     // [buf][mt][kt-parity]
    uint4 b[2][2];        // [buf][nt]
    float acc[2][2][4];
#pragma unroll
    for (int i = 0; i < 2; ++i)
#pragma unroll
        for (int nf = 0; nf < 2; ++nf)
#pragma unroll
            for (int q = 0; q < 4; ++q) acc[i][nf][q] = 0.f;

    auto loadS = [&](int buf, int s) {
        const int kt0 = 2 * s;
        const unsigned char* base;
        int ktl0, mts;
        if (kt0 < XKT) { base = xp; ktl0 = kt0;       mts = XKT * 512; }
        else           { base = hp; ktl0 = kt0 - XKT; mts = 32 * 512;  }
#pragma unroll
        for (int i = 0; i < 2; ++i) {
            const unsigned char* p = base + (size_t)(mtb + i) * mts + (size_t)ktl0 * 512 + lane * 16;
            a[buf][i][0] = *(const uint4*)p;
            a[buf][i][1] = *(const uint4*)(p + 512);
        }
#pragma unroll
        for (int j = 0; j < 2; ++j)
            b[buf][j] = *(const uint4*)(bptr + ((size_t)j * S + s) * 512);
    };

    loadS(0, 0);
#pragma unroll 4
    for (int s = 0; s < S; ++s) {
        const int cb = s & 1;
        if (s + 1 < S) loadS(cb ^ 1, s + 1);
#pragma unroll
        for (int i = 0; i < 2; ++i)
#pragma unroll
            for (int nf = 0; nf < 2; ++nf) {
                mma_f16(acc[i][nf], (const uint32_t*)&a[cb][i][0], b[cb][nf].x, b[cb][nf].y);
                mma_f16(acc[i][nf], (const uint32_t*)&a[cb][i][1], b[cb][nf].z, b[cb][nf].w);
            }
    }

    // ---- epilogue: accs -> smem z [64][68] -> fused cell ----
    __shared__ float zs[64 * 68];
#pragma unroll
    for (int i = 0; i < 2; ++i)
#pragma unroll
        for (int nf = 0; nf < 2; ++nf) {
            int r = mgrp * 32 + i * 16 + (lane >> 2);
            int c = ngrp * 16 + nf * 8 + 2 * (lane & 3);
            *(float2*)&zs[r * 68 + c]       = make_float2(acc[i][nf][0], acc[i][nf][1]);
            *(float2*)&zs[(r + 8) * 68 + c] = make_float2(acc[i][nf][2], acc[i][nf][3]);
        }
    __syncthreads();

    {
        const int row = tid >> 2;                  // 0..63 local batch row
        const int grp = tid & 3;                   // 4-j quarter
        const int bg  = blockIdx.y * 64 + row;     // global batch row
        const int j0  = blockIdx.x * 16 + grp * 4; // global j (4 consecutive)
        const int n0  = blockIdx.x * 64 + grp * 16;

        const float* zrow = &zs[row * 68 + grp * 16];
        float4 cA = *(const float4*)&cst[bg * HIDDEN + j0];
        float cOld[4] = {cA.x, cA.y, cA.z, cA.w};
        float hv[4], cN[4];
#pragma unroll
        for (int q = 0; q < 4; ++q) {
            float4 z4 = *(const float4*)&zrow[q * 4];
            float4 b4 = *(const float4*)&bs[n0 + q * 4];
            float zi = z4.x + b4.x;
            float zf = z4.y + b4.y;
            float zg = z4.z + b4.z;
            float zo = z4.w + b4.w;
            float cn = fsigmoid(zf) * cOld[q] + fsigmoid(zi) * ftanh(zg);
            cN[q] = cn;
            hv[q] = fsigmoid(zo) * ftanh(cn);
        }
        *(float4*)&cst[bg * HIDDEN + j0] = make_float4(cN[0], cN[1], cN[2], cN[3]);

        // packed h store (fragment layout); j0 is 4-aligned
        {
            int kt = j0 >> 4, kkb = j0 & 15;
            int mt = bg >> 4, r = bg & 15;
            int q  = ((r >> 3) & 1) + ((kkb >> 3) & 1) * 2;
            int l0 = ((r & 7) << 2) + ((kkb & 7) >> 1);
            unsigned char* base = hop + ((size_t)(mt * 32 + kt) * 32 + l0) * 16 + q * 4;
            *(uint32_t*)base        = h2u(hv[0], hv[1]);
            *(uint32_t*)(base + 16) = h2u(hv[2], hv[3]);
        }
        if (WPLAIN) {
            __half2 p0 = __floats2half2_rn(hv[0], hv[1]);
            __half2 p1 = __floats2half2_rn(hv[2], hv[3]);
            *(uint2*)&hplain[bg * HIDDEN + j0] =
                make_uint2(*(uint32_t*)&p0, *(uint32_t*)&p1);
        }
    }
}

// ---------------------------------------------------------------------------
// Decoder heads: out[b][t] = h1·fc1 + b1 ; decx_packed = h1·fc4^T + b4
// ---------------------------------------------------------------------------
__global__ __launch_bounds__(256)
void dec_fc(const __half* __restrict__ h1,
            const float* __restrict__ fc1_w, const float* __restrict__ fc1_b,
            const float* __restrict__ fc4_w, const float* __restrict__ fc4_b,
            float* __restrict__ out, int t)
{
    unsigned char* Dp = g_scratch + OFF_DECX;
    __shared__ float sh[HIDDEN];
    const int b = blockIdx.x;
    for (int i = threadIdx.x; i < HIDDEN; i += blockDim.x)
        sh[i] = __half2float(h1[b * HIDDEN + i]);
    __syncthreads();

    const int warp = threadIdx.x >> 5;
    const int lane = threadIdx.x & 31;
    for (int o = warp; o < 1 + NFEAT; o += 8) {
        const float* w = (o == 0) ? fc1_w : (fc4_w + (o - 1) * HIDDEN);
        float s = 0.f;
#pragma unroll 4
        for (int k = lane; k < HIDDEN; k += 32) s += sh[k] * w[k];
#pragma unroll
        for (int off = 16; off; off >>= 1) s += __shfl_down_sync(0xffffffffu, s, off);
        if (lane == 0) {
            if (o == 0) {
                out[b * HORIZONS + t] = s + fc1_b[0];
            } else {
                int f = o - 1;
                float v = s + fc4_b[f];
                int ktl = f >> 4, kk = f & 15;
                int mt = b >> 4, r = b & 15;
                int q  = ((r >> 3) & 1) + ((kk >> 3) & 1) * 2;
                int l0 = ((r & 7) << 2) + ((kk & 7) >> 1);
                unsigned char* addr = Dp + ((size_t)(mt * 2 + ktl) * 32 + l0) * 16
                                      + q * 4 + (kk & 1) * 2;
                *(__half*)addr = __float2half_rn(v);
            }
        }
    }
}

// ---------------------------------------------------------------------------
extern "C" void kernel_launch(void* const* d_in, const int* in_sizes, int n_in,
                              void* d_out, int out_size)
{
    const int wb = (in_sizes[2] == 1) ? 3 : 2;

    const float* src = (const float*)d_in[0];
    WPtrs wp;
    for (int i = 0; i < 16; i++) wp.w[i] = (const float*)d_in[wb + i];
    const float* fc1_w = (const float*)d_in[wb + 16];
    const float* fc1_b = (const float*)d_in[wb + 17];
    const float* fc4_w = (const float*)d_in[wb + 18];
    const float* fc4_b = (const float*)d_in[wb + 19];
    float* out = (float*)d_out;

    unsigned char* S = nullptr;
    cudaGetSymbolAddress((void**)&S, g_scratch);

    unsigned char* B0 = S + OFF_B0;
    unsigned char* B1 = S + OFF_B1;
    unsigned char* B2 = S + OFF_B2;
    unsigned char* B3 = S + OFF_B3;
    float* BS = (float*)(S + OFF_BS);
    unsigned char* H0PK[2] = {S + OFF_H0PK, S + OFF_H0PK + HPK_BYTES};
    unsigned char* H1PK[2] = {S + OFF_H1PK, S + OFF_H1PK + HPK_BYTES};
    float* C0 = (float*)(S + OFF_C);
    float* C1 = C0 + 512 * 512;
    unsigned char* XPK  = S + OFF_XPK;
    unsigned char* DECX = S + OFF_DECX;
    __half* H1PL = (__half*)(S + OFF_H1PL);

    // launch #1, #2  ->  ncu -s 5 lands on launch #6 = l1(t=1)
    setup_all<<<1024, 256>>>(src, wp);
    init_decx_pk<<<(32 * 2 * 128 + 255) / 256, 256>>>(src);

    dim3 grid(32, 8);   // 256 CTAs, 256 threads each

    for (int t = 0; t < LAGS; t++) {
        lstm_step_dl<S_L0, 2, false><<<grid, 256>>>(
            XPK + (size_t)t * XPK_T, H0PK[t & 1], B0, BS + 0 * NGATE,
            C0, H0PK[(t + 1) & 1], nullptr);
        lstm_step_dl<S_L1, 32, false><<<grid, 256>>>(
            H0PK[(t + 1) & 1], H1PK[t & 1], B1, BS + 1 * NGATE,
            C1, H1PK[(t + 1) & 1], nullptr);
    }

    for (int tt = 0; tt < HORIZONS; tt++) {
        int t = LAGS + tt;
        lstm_step_dl<S_L0, 2, false><<<grid, 256>>>(
            DECX, H0PK[t & 1], B2, BS + 2 * NGATE,
            C0, H0PK[(t + 1) & 1], nullptr);
        lstm_step_dl<S_L1, 32, true><<<grid, 256>>>(
            H0PK[(t + 1) & 1], H1PK[t & 1], B3, BS + 3 * NGATE,
            C1, H1PK[(t + 1) & 1], H1PL);
        dec_fc<<<BATCH, 256>>>(H1PL, fc1_w, fc1_b, fc4_w, fc4_b, out, tt);
    }
}